// round 4
// baseline (speedup 1.0000x reference)
#include <cuda_runtime.h>
#include <cstdint>

// Problem constants
#define T_  4
#define B_  4
#define N_  1024
#define D_  512
#define H_  8
#define HD_ 64
#define M_  (T_*B_*N_)   // 16384 rows

// Scratch (no cudaMalloc allowed)
__device__ float g_q  [(size_t)M_*D_];
__device__ float g_k  [(size_t)M_*D_];
__device__ float g_v  [(size_t)M_*D_];
__device__ float g_ctx[(size_t)M_*D_];

// ---------------------------------------------------------------------------
// TF32 helpers
// ---------------------------------------------------------------------------
__device__ __forceinline__ uint32_t f2tf32(float x) {
    uint32_t y;
    asm("cvt.rna.tf32.f32 %0, %1;" : "=r"(y) : "f"(x));
    return y;
}
__device__ __forceinline__ void split_tf32(float x, uint32_t& hi, uint32_t& lo) {
    hi = f2tf32(x);
    float r = x - __uint_as_float(hi);
    lo = f2tf32(r);
}
__device__ __forceinline__ void mma_tf32(float c[4], const uint32_t a[4],
                                         uint32_t b0, uint32_t b1) {
    asm volatile(
        "mma.sync.aligned.m16n8k8.row.col.f32.tf32.tf32.f32 "
        "{%0,%1,%2,%3}, {%4,%5,%6,%7}, {%8,%9}, {%0,%1,%2,%3};"
        : "+f"(c[0]), "+f"(c[1]), "+f"(c[2]), "+f"(c[3])
        : "r"(a[0]), "r"(a[1]), "r"(a[2]), "r"(a[3]), "r"(b0), "r"(b1));
}
// 3-term split product: C += hi*hi + hi*lo + lo*hi  (~fp32 accuracy)
__device__ __forceinline__ void mma3(float c[4],
                                     const uint32_t ah[4], const uint32_t al[4],
                                     uint32_t bh0, uint32_t bh1,
                                     uint32_t bl0, uint32_t bl1) {
    mma_tf32(c, ah, bh0, bh1);
    mma_tf32(c, ah, bl0, bl1);
    mma_tf32(c, al, bh0, bh1);
}

// ---------------------------------------------------------------------------
// Tensor-core GEMM: C[M,Nc] = A[M,K] @ W[Nc,K]^T + bias  (3xTF32 split)
// ---------------------------------------------------------------------------
__global__ __launch_bounds__(256) void gemm_mma_kernel(
    const float* __restrict__ A, const float* __restrict__ W,
    const float* __restrict__ bias, float* __restrict__ C,
    int M, int Nc, int K)
{
    __shared__ float As[128][36];
    __shared__ float Ws[128][36];

    const int tid  = threadIdx.x;
    const int lane = tid & 31, warp = tid >> 5;
    const int g    = lane >> 2, tg = lane & 3;
    const int wm   = (warp >> 1) * 32;
    const int wn   = (warp & 1) * 64;
    const int mb   = blockIdx.y * 128, nb = blockIdx.x * 128;

    float acc[2][8][4];
    #pragma unroll
    for (int i = 0; i < 2; i++)
        #pragma unroll
        for (int j = 0; j < 8; j++)
            #pragma unroll
            for (int l = 0; l < 4; l++) acc[i][j][l] = 0.f;

    for (int kb = 0; kb < K; kb += 32) {
        #pragma unroll
        for (int l = tid; l < 1024; l += 256) {
            int r = l >> 3, c4 = (l & 7) * 4;
            *(float4*)&As[r][c4] = *(const float4*)&A[(size_t)(mb + r) * K + kb + c4];
        }
        #pragma unroll
        for (int l = tid; l < 1024; l += 256) {
            int r = l >> 3, c4 = (l & 7) * 4;
            *(float4*)&Ws[r][c4] = *(const float4*)&W[(size_t)(nb + r) * K + kb + c4];
        }
        __syncthreads();

        #pragma unroll
        for (int k8 = 0; k8 < 32; k8 += 8) {
            uint32_t ahi[2][4], alo[2][4];
            #pragma unroll
            for (int mi = 0; mi < 2; mi++) {
                int m = wm + mi * 16;
                split_tf32(As[m + g    ][k8 + tg    ], ahi[mi][0], alo[mi][0]);
                split_tf32(As[m + g + 8][k8 + tg    ], ahi[mi][1], alo[mi][1]);
                split_tf32(As[m + g    ][k8 + tg + 4], ahi[mi][2], alo[mi][2]);
                split_tf32(As[m + g + 8][k8 + tg + 4], ahi[mi][3], alo[mi][3]);
            }
            #pragma unroll
            for (int nj = 0; nj < 8; nj++) {
                int n = wn + nj * 8;
                uint32_t bh0, bl0, bh1, bl1;
                split_tf32(Ws[n + g][k8 + tg    ], bh0, bl0);
                split_tf32(Ws[n + g][k8 + tg + 4], bh1, bl1);
                #pragma unroll
                for (int mi = 0; mi < 2; mi++)
                    mma3(acc[mi][nj], ahi[mi], alo[mi], bh0, bh1, bl0, bl1);
            }
        }
        __syncthreads();
    }

    #pragma unroll
    for (int mi = 0; mi < 2; mi++) {
        int r0 = mb + wm + mi * 16 + g;
        #pragma unroll
        for (int nj = 0; nj < 8; nj++) {
            int c0 = nb + wn + nj * 8 + 2 * tg;
            float bia0 = bias[c0], bia1 = bias[c0 + 1];
            C[(size_t)r0 * Nc + c0    ]       = acc[mi][nj][0] + bia0;
            C[(size_t)r0 * Nc + c0 + 1]       = acc[mi][nj][1] + bia1;
            C[(size_t)(r0 + 8) * Nc + c0    ] = acc[mi][nj][2] + bia0;
            C[(size_t)(r0 + 8) * Nc + c0 + 1] = acc[mi][nj][3] + bia1;
        }
    }
}

// ---------------------------------------------------------------------------
// Tensor-core ReLU-normalized attention.
// Block: 64 queries of one (t,b,h); stream 32-key tiles.
//   S = Q K^T (MMA, 3-split) ; P = relu(S/8) -> smem (overlays K buffer)
//   denom += rowsum(P) (register + shfl reduce)
//   acc += P V (MMA, 3-split)
// Warps: 4 (M) x 2 (N). S: warp 16q x 16keys. PV: warp 16q x 32hd.
// ---------------------------------------------------------------------------
__global__ __launch_bounds__(256) void attn_mma_kernel(
    const float* __restrict__ q, const float* __restrict__ k,
    const float* __restrict__ v, float* __restrict__ ctx)
{
    __shared__ float Qs[64][68];     // [query][hd]
    __shared__ float KP[2304];       // K view: [32][68] ; P view: [64][36]
    __shared__ float Vs[32][68];     // [key][hd]
    __shared__ float dsm[2][64];     // per-wx partial denominators

    const int tid  = threadIdx.x;
    const int lane = tid & 31, warp = tid >> 5;
    const int g    = lane >> 2, tg = lane & 3;
    const int wy   = warp >> 1, wx = warp & 1;
    const int wm   = wy * 16;

    const int hidx = blockIdx.y;
    const int h    = hidx & (H_ - 1);
    const int tb   = hidx >> 3;
    const size_t base = (size_t)tb * N_ * D_ + (size_t)h * HD_;
    const int q0   = blockIdx.x * 64;

    // Load Q tile 64x64 (float4)
    #pragma unroll
    for (int l = tid; l < 64 * 16; l += 256) {
        int r = l >> 4, c4 = (l & 15) * 4;
        *(float4*)&Qs[r][c4] = *(const float4*)&q[base + (size_t)(q0 + r) * D_ + c4];
    }

    float accPV[4][4];
    #pragma unroll
    for (int j = 0; j < 4; j++)
        #pragma unroll
        for (int l = 0; l < 4; l++) accPV[j][l] = 0.f;
    float d0 = 0.f, d1 = 0.f;

    for (int k0 = 0; k0 < N_; k0 += 32) {
        // Load K,V tiles 32x64 (float4)
        #pragma unroll
        for (int l = tid; l < 32 * 16; l += 256) {
            int r = l >> 4, c4 = (l & 15) * 4;
            *(float4*)&KP[r * 68 + c4] = *(const float4*)&k[base + (size_t)(k0 + r) * D_ + c4];
        }
        #pragma unroll
        for (int l = tid; l < 32 * 16; l += 256) {
            int r = l >> 4, c4 = (l & 15) * 4;
            *(float4*)&Vs[r][c4] = *(const float4*)&v[base + (size_t)(k0 + r) * D_ + c4];
        }
        __syncthreads();

        // ---- S = Q K^T : 64q x 32keys, contraction over HD=64 ----
        float accS[2][4];
        #pragma unroll
        for (int j = 0; j < 2; j++)
            #pragma unroll
            for (int l = 0; l < 4; l++) accS[j][l] = 0.f;

        #pragma unroll
        for (int k8 = 0; k8 < 64; k8 += 8) {
            uint32_t ah[4], al[4];
            split_tf32(Qs[wm + g    ][k8 + tg    ], ah[0], al[0]);
            split_tf32(Qs[wm + g + 8][k8 + tg    ], ah[1], al[1]);
            split_tf32(Qs[wm + g    ][k8 + tg + 4], ah[2], al[2]);
            split_tf32(Qs[wm + g + 8][k8 + tg + 4], ah[3], al[3]);
            #pragma unroll
            for (int nj = 0; nj < 2; nj++) {
                int n = wx * 16 + nj * 8;
                uint32_t bh0, bl0, bh1, bl1;
                split_tf32(KP[(n + g) * 68 + k8 + tg    ], bh0, bl0);
                split_tf32(KP[(n + g) * 68 + k8 + tg + 4], bh1, bl1);
                mma3(accS[nj], ah, al, bh0, bh1, bl0, bl1);
            }
        }
        __syncthreads();   // all warps done reading K before P overwrites it

        // ---- P = relu(S * 0.125) -> smem ; denominator accumulation ----
        #pragma unroll
        for (int nj = 0; nj < 2; nj++) {
            int key0 = wx * 16 + nj * 8 + 2 * tg;
            float p0 = fmaxf(accS[nj][0] * 0.125f, 0.f);
            float p1 = fmaxf(accS[nj][1] * 0.125f, 0.f);
            float p2 = fmaxf(accS[nj][2] * 0.125f, 0.f);
            float p3 = fmaxf(accS[nj][3] * 0.125f, 0.f);
            KP[(wm + g    ) * 36 + key0    ] = p0;
            KP[(wm + g    ) * 36 + key0 + 1] = p1;
            KP[(wm + g + 8) * 36 + key0    ] = p2;
            KP[(wm + g + 8) * 36 + key0 + 1] = p3;
            d0 += p0 + p1;
            d1 += p2 + p3;
        }
        __syncthreads();

        // ---- acc += P V : 64q x 64hd, contraction over 32 keys ----
        #pragma unroll
        for (int k8 = 0; k8 < 32; k8 += 8) {
            uint32_t ah[4], al[4];
            split_tf32(KP[(wm + g    ) * 36 + k8 + tg    ], ah[0], al[0]);
            split_tf32(KP[(wm + g + 8) * 36 + k8 + tg    ], ah[1], al[1]);
            split_tf32(KP[(wm + g    ) * 36 + k8 + tg + 4], ah[2], al[2]);
            split_tf32(KP[(wm + g + 8) * 36 + k8 + tg + 4], ah[3], al[3]);
            #pragma unroll
            for (int nj = 0; nj < 4; nj++) {
                int n = wx * 32 + nj * 8;
                uint32_t bh0, bl0, bh1, bl1;
                split_tf32(Vs[k8 + tg    ][n + g], bh0, bl0);
                split_tf32(Vs[k8 + tg + 4][n + g], bh1, bl1);
                mma3(accPV[nj], ah, al, bh0, bh1, bl0, bl1);
            }
        }
        __syncthreads();   // before next tile overwrites KP/Vs
    }

    // ---- denominator reduce: over tg lanes, then over wx warps ----
    d0 += __shfl_xor_sync(0xffffffffu, d0, 1);
    d0 += __shfl_xor_sync(0xffffffffu, d0, 2);
    d1 += __shfl_xor_sync(0xffffffffu, d1, 1);
    d1 += __shfl_xor_sync(0xffffffffu, d1, 2);
    if (tg == 0) {
        dsm[wx][wm + g    ] = d0;
        dsm[wx][wm + g + 8] = d1;
    }
    __syncthreads();

    const int row0 = wm + g, row1 = wm + g + 8;
    const float inv0 = 1.f / (dsm[0][row0] + dsm[1][row0] + 1e-6f);
    const float inv1 = 1.f / (dsm[0][row1] + dsm[1][row1] + 1e-6f);

    #pragma unroll
    for (int nj = 0; nj < 4; nj++) {
        int col = wx * 32 + nj * 8 + 2 * tg;
        size_t o0 = base + (size_t)(q0 + row0) * D_ + col;
        size_t o1 = base + (size_t)(q0 + row1) * D_ + col;
        ctx[o0    ] = accPV[nj][0] * inv0;
        ctx[o0 + 1] = accPV[nj][1] * inv0;
        ctx[o1    ] = accPV[nj][2] * inv1;
        ctx[o1 + 1] = accPV[nj][3] * inv1;
    }
}

// ---------------------------------------------------------------------------
// Launcher. Input order: x, wq, bq, wk, bk, wv, bv, wo, bo
// ---------------------------------------------------------------------------
extern "C" void kernel_launch(void* const* d_in, const int* in_sizes, int n_in,
                              void* d_out, int out_size)
{
    const float* x  = (const float*)d_in[0];
    const float* wq = (const float*)d_in[1];
    const float* bq = (const float*)d_in[2];
    const float* wk = (const float*)d_in[3];
    const float* bk = (const float*)d_in[4];
    const float* wv = (const float*)d_in[5];
    const float* bv = (const float*)d_in[6];
    const float* wo = (const float*)d_in[7];
    const float* bo = (const float*)d_in[8];
    float* out = (float*)d_out;

    float *q, *k, *v, *ctx;
    cudaGetSymbolAddress((void**)&q,   g_q);
    cudaGetSymbolAddress((void**)&k,   g_k);
    cudaGetSymbolAddress((void**)&v,   g_v);
    cudaGetSymbolAddress((void**)&ctx, g_ctx);

    dim3 blk(256);
    dim3 gProj(D_ / 128, M_ / 128);        // 4 x 128
    gemm_mma_kernel<<<gProj, blk>>>(x, wq, bq, q, M_, D_, D_);
    gemm_mma_kernel<<<gProj, blk>>>(x, wk, bk, k, M_, D_, D_);
    gemm_mma_kernel<<<gProj, blk>>>(x, wv, bv, v, M_, D_, D_);

    dim3 gAttn(N_ / 64, T_ * B_ * H_);     // 16 x 128
    attn_mma_kernel<<<gAttn, blk>>>(q, k, v, ctx);

    gemm_mma_kernel<<<gProj, blk>>>(ctx, wo, bo, out, M_, D_, D_);
}

// round 5
// speedup vs baseline: 1.1213x; 1.1213x over previous
#include <cuda_runtime.h>
#include <cstdint>

// Problem constants
#define T_  4
#define B_  4
#define N_  1024
#define D_  512
#define H_  8
#define HD_ 64
#define M_  (T_*B_*N_)   // 16384 rows
#define D2_ (2*D_)       // packed (hi,lo) row width

// Scratch (no cudaMalloc allowed). q/k/v stored pre-split: (hi,lo) adjacent.
__device__ float g_q2 [(size_t)M_*D2_];
__device__ float g_k2 [(size_t)M_*D2_];
__device__ float g_v2 [(size_t)M_*D2_];
__device__ float g_ctx[(size_t)M_*D_];

// ---------------------------------------------------------------------------
// TF32 helpers
// ---------------------------------------------------------------------------
__device__ __forceinline__ uint32_t f2tf32(float x) {
    uint32_t y;
    asm("cvt.rna.tf32.f32 %0, %1;" : "=r"(y) : "f"(x));
    return y;
}
__device__ __forceinline__ void split_tf32(float x, uint32_t& hi, uint32_t& lo) {
    hi = f2tf32(x);
    float r = x - __uint_as_float(hi);
    lo = f2tf32(r);
}
__device__ __forceinline__ void mma_tf32(float c[4], const uint32_t a[4],
                                         uint32_t b0, uint32_t b1) {
    asm volatile(
        "mma.sync.aligned.m16n8k8.row.col.f32.tf32.tf32.f32 "
        "{%0,%1,%2,%3}, {%4,%5,%6,%7}, {%8,%9}, {%0,%1,%2,%3};"
        : "+f"(c[0]), "+f"(c[1]), "+f"(c[2]), "+f"(c[3])
        : "r"(a[0]), "r"(a[1]), "r"(a[2]), "r"(a[3]), "r"(b0), "r"(b1));
}
// 3-term split product: C += Ah*Bh + Ah*Bl + Al*Bh  (~fp32 accuracy)
__device__ __forceinline__ void mma3(float c[4],
                                     const uint32_t ah[4], const uint32_t al[4],
                                     uint32_t bh0, uint32_t bh1,
                                     uint32_t bl0, uint32_t bl1) {
    mma_tf32(c, ah, bh0, bh1);
    mma_tf32(c, ah, bl0, bl1);
    mma_tf32(c, al, bh0, bh1);
}
__device__ __forceinline__ uint32_t fu(float x) { return __float_as_uint(x); }

// ---------------------------------------------------------------------------
// Tensor-core GEMM: C = A[M,K] @ W[Nc,K]^T + bias  (3xTF32 split)
// SPLITOUT=0: plain float C[M][Nc].
// SPLITOUT=1: packed pre-split C2[M][2*Nc], (hi,lo) adjacent per element.
// ---------------------------------------------------------------------------
template<int SPLITOUT>
__global__ __launch_bounds__(256) void gemm_mma_kernel(
    const float* __restrict__ A, const float* __restrict__ W,
    const float* __restrict__ bias, float* __restrict__ C,
    int M, int Nc, int K)
{
    __shared__ float As[128][36];
    __shared__ float Ws[128][36];

    const int tid  = threadIdx.x;
    const int lane = tid & 31, warp = tid >> 5;
    const int g    = lane >> 2, tg = lane & 3;
    const int wm   = (warp >> 1) * 32;
    const int wn   = (warp & 1) * 64;
    const int mb   = blockIdx.y * 128, nb = blockIdx.x * 128;

    float acc[2][8][4];
    #pragma unroll
    for (int i = 0; i < 2; i++)
        #pragma unroll
        for (int j = 0; j < 8; j++)
            #pragma unroll
            for (int l = 0; l < 4; l++) acc[i][j][l] = 0.f;

    for (int kb = 0; kb < K; kb += 32) {
        #pragma unroll
        for (int l = tid; l < 1024; l += 256) {
            int r = l >> 3, c4 = (l & 7) * 4;
            *(float4*)&As[r][c4] = *(const float4*)&A[(size_t)(mb + r) * K + kb + c4];
        }
        #pragma unroll
        for (int l = tid; l < 1024; l += 256) {
            int r = l >> 3, c4 = (l & 7) * 4;
            *(float4*)&Ws[r][c4] = *(const float4*)&W[(size_t)(nb + r) * K + kb + c4];
        }
        __syncthreads();

        #pragma unroll
        for (int k8 = 0; k8 < 32; k8 += 8) {
            uint32_t ahi[2][4], alo[2][4];
            #pragma unroll
            for (int mi = 0; mi < 2; mi++) {
                int m = wm + mi * 16;
                split_tf32(As[m + g    ][k8 + tg    ], ahi[mi][0], alo[mi][0]);
                split_tf32(As[m + g + 8][k8 + tg    ], ahi[mi][1], alo[mi][1]);
                split_tf32(As[m + g    ][k8 + tg + 4], ahi[mi][2], alo[mi][2]);
                split_tf32(As[m + g + 8][k8 + tg + 4], ahi[mi][3], alo[mi][3]);
            }
            #pragma unroll
            for (int nj = 0; nj < 8; nj++) {
                int n = wn + nj * 8;
                uint32_t bh0, bl0, bh1, bl1;
                split_tf32(Ws[n + g][k8 + tg    ], bh0, bl0);
                split_tf32(Ws[n + g][k8 + tg + 4], bh1, bl1);
                #pragma unroll
                for (int mi = 0; mi < 2; mi++)
                    mma3(acc[mi][nj], ahi[mi], alo[mi], bh0, bh1, bl0, bl1);
            }
        }
        __syncthreads();
    }

    #pragma unroll
    for (int mi = 0; mi < 2; mi++) {
        int r0 = mb + wm + mi * 16 + g;
        #pragma unroll
        for (int nj = 0; nj < 8; nj++) {
            int c0 = nb + wn + nj * 8 + 2 * tg;
            float bia0 = bias[c0], bia1 = bias[c0 + 1];
            float v00 = acc[mi][nj][0] + bia0;
            float v01 = acc[mi][nj][1] + bia1;
            float v10 = acc[mi][nj][2] + bia0;
            float v11 = acc[mi][nj][3] + bia1;
            if (SPLITOUT) {
                uint32_t h0, l0, h1, l1;
                split_tf32(v00, h0, l0); split_tf32(v01, h1, l1);
                *(float4*)&C[(size_t)r0 * 2 * Nc + 2 * c0] =
                    make_float4(__uint_as_float(h0), __uint_as_float(l0),
                                __uint_as_float(h1), __uint_as_float(l1));
                split_tf32(v10, h0, l0); split_tf32(v11, h1, l1);
                *(float4*)&C[(size_t)(r0 + 8) * 2 * Nc + 2 * c0] =
                    make_float4(__uint_as_float(h0), __uint_as_float(l0),
                                __uint_as_float(h1), __uint_as_float(l1));
            } else {
                C[(size_t)r0 * Nc + c0    ]       = v00;
                C[(size_t)r0 * Nc + c0 + 1]       = v01;
                C[(size_t)(r0 + 8) * Nc + c0    ] = v10;
                C[(size_t)(r0 + 8) * Nc + c0 + 1] = v11;
            }
        }
    }
}

// ---------------------------------------------------------------------------
// Tensor-core ReLU-normalized attention on pre-split packed q/k/v.
// Block: 64 queries of one (t,b,h); stream 32-key tiles.
// Smem (dynamic, 87 KB): Q2[64][134] K2[32][134] V2[32][134] P2[64][70] dsm[2][64]
// Packed element (hi,lo) = one float2 -> one LDS.64 per fragment element.
// ---------------------------------------------------------------------------
#define QSTR 134   // row stride (floats) for 64-wide packed rows
#define PSTR 70    // row stride (floats) for 32-wide packed P rows
#define SM_Q  0
#define SM_K  (64*QSTR)
#define SM_V  (SM_K + 32*QSTR)
#define SM_P  (SM_V + 32*QSTR)
#define SM_D  (SM_P + 64*PSTR)
#define SM_TOT (SM_D + 128)          // floats

__global__ __launch_bounds__(256) void attn_mma2_kernel(
    const float* __restrict__ q2, const float* __restrict__ k2,
    const float* __restrict__ v2, float* __restrict__ ctx)
{
    extern __shared__ float sm[];
    float* Q2  = sm + SM_Q;
    float* K2s = sm + SM_K;
    float* V2s = sm + SM_V;
    float* P2  = sm + SM_P;
    float* dsm = sm + SM_D;

    const int tid  = threadIdx.x;
    const int lane = tid & 31, warp = tid >> 5;
    const int g    = lane >> 2, tg = lane & 3;
    const int wy   = warp >> 1, wx = warp & 1;
    const int wm   = wy * 16;

    const int hidx = blockIdx.y;
    const int h    = hidx & (H_ - 1);
    const int tb   = hidx >> 3;
    const size_t base2 = (size_t)tb * N_ * D2_ + (size_t)h * (2 * HD_);
    const size_t baseo = (size_t)tb * N_ * D_  + (size_t)h * HD_;
    const int q0   = blockIdx.x * 64;

    // Load packed Q tile: 64 rows x 128 floats
    #pragma unroll
    for (int l = tid; l < 64 * 32; l += 256) {
        int r = l >> 5, c4 = (l & 31) * 4;
        float4 t = *(const float4*)&q2[base2 + (size_t)(q0 + r) * D2_ + c4];
        float* dst = &Q2[r * QSTR + c4];
        *(float2*)dst       = make_float2(t.x, t.y);
        *(float2*)(dst + 2) = make_float2(t.z, t.w);
    }

    float accPV[4][4];
    #pragma unroll
    for (int j = 0; j < 4; j++)
        #pragma unroll
        for (int l = 0; l < 4; l++) accPV[j][l] = 0.f;
    float d0 = 0.f, d1 = 0.f;

    const float* qrow0 = &Q2[(wm + g) * QSTR];
    const float* qrow1 = qrow0 + 8 * QSTR;
    const float* prow0 = &P2[(wm + g) * PSTR];
    const float* prow1 = prow0 + 8 * PSTR;

    for (int k0 = 0; k0 < N_; k0 += 32) {
        // Load packed K,V tiles: 32 rows x 128 floats each
        #pragma unroll
        for (int l = tid; l < 32 * 32; l += 256) {
            int r = l >> 5, c4 = (l & 31) * 4;
            float4 t = *(const float4*)&k2[base2 + (size_t)(k0 + r) * D2_ + c4];
            float* dst = &K2s[r * QSTR + c4];
            *(float2*)dst       = make_float2(t.x, t.y);
            *(float2*)(dst + 2) = make_float2(t.z, t.w);
        }
        #pragma unroll
        for (int l = tid; l < 32 * 32; l += 256) {
            int r = l >> 5, c4 = (l & 31) * 4;
            float4 t = *(const float4*)&v2[base2 + (size_t)(k0 + r) * D2_ + c4];
            float* dst = &V2s[r * QSTR + c4];
            *(float2*)dst       = make_float2(t.x, t.y);
            *(float2*)(dst + 2) = make_float2(t.z, t.w);
        }
        __syncthreads();

        // ---- S = Q K^T : 64q x 32keys, contraction over HD=64 ----
        float accS[2][4];
        #pragma unroll
        for (int j = 0; j < 2; j++)
            #pragma unroll
            for (int l = 0; l < 4; l++) accS[j][l] = 0.f;

        #pragma unroll
        for (int k8 = 0; k8 < 64; k8 += 8) {
            float2 a0 = *(const float2*)&qrow0[2 * (k8 + tg)];
            float2 a1 = *(const float2*)&qrow1[2 * (k8 + tg)];
            float2 a2 = *(const float2*)&qrow0[2 * (k8 + tg + 4)];
            float2 a3 = *(const float2*)&qrow1[2 * (k8 + tg + 4)];
            uint32_t ah[4] = { fu(a0.x), fu(a1.x), fu(a2.x), fu(a3.x) };
            uint32_t al[4] = { fu(a0.y), fu(a1.y), fu(a2.y), fu(a3.y) };
            #pragma unroll
            for (int nj = 0; nj < 2; nj++) {
                const float* krow = &K2s[(wx * 16 + nj * 8 + g) * QSTR];
                float2 b0 = *(const float2*)&krow[2 * (k8 + tg)];
                float2 b1 = *(const float2*)&krow[2 * (k8 + tg + 4)];
                mma3(accS[nj], ah, al, fu(b0.x), fu(b1.x), fu(b0.y), fu(b1.y));
            }
        }

        // ---- P = relu(S * 0.125) -> packed smem ; denom accumulation ----
        #pragma unroll
        for (int nj = 0; nj < 2; nj++) {
            int key0 = wx * 16 + nj * 8 + 2 * tg;
            float p0 = fmaxf(accS[nj][0] * 0.125f, 0.f);
            float p1 = fmaxf(accS[nj][1] * 0.125f, 0.f);
            float p2 = fmaxf(accS[nj][2] * 0.125f, 0.f);
            float p3 = fmaxf(accS[nj][3] * 0.125f, 0.f);
            uint32_t hh, ll;
            split_tf32(p0, hh, ll);
            *(float2*)&P2[(wm + g) * PSTR + 2 * key0] =
                make_float2(__uint_as_float(hh), __uint_as_float(ll));
            split_tf32(p1, hh, ll);
            *(float2*)&P2[(wm + g) * PSTR + 2 * key0 + 2] =
                make_float2(__uint_as_float(hh), __uint_as_float(ll));
            split_tf32(p2, hh, ll);
            *(float2*)&P2[(wm + g + 8) * PSTR + 2 * key0] =
                make_float2(__uint_as_float(hh), __uint_as_float(ll));
            split_tf32(p3, hh, ll);
            *(float2*)&P2[(wm + g + 8) * PSTR + 2 * key0 + 2] =
                make_float2(__uint_as_float(hh), __uint_as_float(ll));
            d0 += p0 + p1;
            d1 += p2 + p3;
        }
        __syncthreads();

        // ---- acc += P V : 64q x 64hd, contraction over 32 keys ----
        #pragma unroll
        for (int k8 = 0; k8 < 32; k8 += 8) {
            float2 a0 = *(const float2*)&prow0[2 * (k8 + tg)];
            float2 a1 = *(const float2*)&prow1[2 * (k8 + tg)];
            float2 a2 = *(const float2*)&prow0[2 * (k8 + tg + 4)];
            float2 a3 = *(const float2*)&prow1[2 * (k8 + tg + 4)];
            uint32_t ah[4] = { fu(a0.x), fu(a1.x), fu(a2.x), fu(a3.x) };
            uint32_t al[4] = { fu(a0.y), fu(a1.y), fu(a2.y), fu(a3.y) };
            #pragma unroll
            for (int nj = 0; nj < 4; nj++) {
                int n = wx * 32 + nj * 8;
                float2 b0 = *(const float2*)&V2s[(k8 + tg    ) * QSTR + 2 * (n + g)];
                float2 b1 = *(const float2*)&V2s[(k8 + tg + 4) * QSTR + 2 * (n + g)];
                mma3(accPV[nj], ah, al, fu(b0.x), fu(b1.x), fu(b0.y), fu(b1.y));
            }
        }
        __syncthreads();   // before next tile overwrites K2s/V2s
    }

    // ---- denominator reduce ----
    d0 += __shfl_xor_sync(0xffffffffu, d0, 1);
    d0 += __shfl_xor_sync(0xffffffffu, d0, 2);
    d1 += __shfl_xor_sync(0xffffffffu, d1, 1);
    d1 += __shfl_xor_sync(0xffffffffu, d1, 2);
    if (tg == 0) {
        dsm[wx * 64 + wm + g    ] = d0;
        dsm[wx * 64 + wm + g + 8] = d1;
    }
    __syncthreads();

    const int row0 = wm + g, row1 = wm + g + 8;
    const float inv0 = 1.f / (dsm[row0] + dsm[64 + row0] + 1e-6f);
    const float inv1 = 1.f / (dsm[row1] + dsm[64 + row1] + 1e-6f);

    #pragma unroll
    for (int nj = 0; nj < 4; nj++) {
        int col = wx * 32 + nj * 8 + 2 * tg;
        size_t o0 = baseo + (size_t)(q0 + row0) * D_ + col;
        size_t o1 = baseo + (size_t)(q0 + row1) * D_ + col;
        ctx[o0    ] = accPV[nj][0] * inv0;
        ctx[o0 + 1] = accPV[nj][1] * inv0;
        ctx[o1    ] = accPV[nj][2] * inv1;
        ctx[o1 + 1] = accPV[nj][3] * inv1;
    }
}

// ---------------------------------------------------------------------------
// Launcher. Input order: x, wq, bq, wk, bk, wv, bv, wo, bo
// ---------------------------------------------------------------------------
extern "C" void kernel_launch(void* const* d_in, const int* in_sizes, int n_in,
                              void* d_out, int out_size)
{
    const float* x  = (const float*)d_in[0];
    const float* wq = (const float*)d_in[1];
    const float* bq = (const float*)d_in[2];
    const float* wk = (const float*)d_in[3];
    const float* bk = (const float*)d_in[4];
    const float* wv = (const float*)d_in[5];
    const float* bv = (const float*)d_in[6];
    const float* wo = (const float*)d_in[7];
    const float* bo = (const float*)d_in[8];
    float* out = (float*)d_out;

    float *q2, *k2, *v2, *ctx;
    cudaGetSymbolAddress((void**)&q2,  g_q2);
    cudaGetSymbolAddress((void**)&k2,  g_k2);
    cudaGetSymbolAddress((void**)&v2,  g_v2);
    cudaGetSymbolAddress((void**)&ctx, g_ctx);

    const int smem_bytes = SM_TOT * (int)sizeof(float);   // 87,040 B
    cudaFuncSetAttribute(attn_mma2_kernel,
                         cudaFuncAttributeMaxDynamicSharedMemorySize, smem_bytes);

    dim3 blk(256);
    dim3 gProj(D_ / 128, M_ / 128);        // 4 x 128
    gemm_mma_kernel<1><<<gProj, blk>>>(x, wq, bq, q2, M_, D_, D_);
    gemm_mma_kernel<1><<<gProj, blk>>>(x, wk, bk, k2, M_, D_, D_);
    gemm_mma_kernel<1><<<gProj, blk>>>(x, wv, bv, v2, M_, D_, D_);

    dim3 gAttn(N_ / 64, T_ * B_ * H_);     // 16 x 128
    attn_mma2_kernel<<<gAttn, blk, smem_bytes>>>(q2, k2, v2, ctx);

    gemm_mma_kernel<0><<<gProj, blk>>>(ctx, wo, bo, out, M_, D_, D_);
}

// round 6
// speedup vs baseline: 1.2520x; 1.1166x over previous
#include <cuda_runtime.h>
#include <cstdint>

// Problem constants
#define T_  4
#define B_  4
#define N_  1024
#define D_  512
#define H_  8
#define HD_ 64
#define M_  (T_*B_*N_)   // 16384 rows
#define D2_ (2*D_)       // packed (hi,lo) row width = 1024 floats

// Scratch (no cudaMalloc allowed). All "2" buffers are pre-split (hi,lo) packed.
__device__ float g_x2 [(size_t)M_*D2_];   // x pre-split; later reused as ctx2
__device__ float g_q2 [(size_t)M_*D2_];
__device__ float g_k2 [(size_t)M_*D2_];
__device__ float g_v2 [(size_t)M_*D2_];
__device__ float g_wq2[(size_t)D_*D2_];
__device__ float g_wk2[(size_t)D_*D2_];
__device__ float g_wv2[(size_t)D_*D2_];
__device__ float g_wo2[(size_t)D_*D2_];

// ---------------------------------------------------------------------------
// TF32 helpers
// ---------------------------------------------------------------------------
__device__ __forceinline__ uint32_t f2tf32(float x) {
    uint32_t y;
    asm("cvt.rna.tf32.f32 %0, %1;" : "=r"(y) : "f"(x));
    return y;
}
__device__ __forceinline__ void split_tf32(float x, uint32_t& hi, uint32_t& lo) {
    hi = f2tf32(x);
    float r = x - __uint_as_float(hi);
    lo = f2tf32(r);
}
__device__ __forceinline__ void mma_tf32(float c[4], const uint32_t a[4],
                                         uint32_t b0, uint32_t b1) {
    asm volatile(
        "mma.sync.aligned.m16n8k8.row.col.f32.tf32.tf32.f32 "
        "{%0,%1,%2,%3}, {%4,%5,%6,%7}, {%8,%9}, {%0,%1,%2,%3};"
        : "+f"(c[0]), "+f"(c[1]), "+f"(c[2]), "+f"(c[3])
        : "r"(a[0]), "r"(a[1]), "r"(a[2]), "r"(a[3]), "r"(b0), "r"(b1));
}
// 3-term split product: C += Ah*Bh + Ah*Bl + Al*Bh  (~fp32 accuracy)
__device__ __forceinline__ void mma3(float c[4],
                                     const uint32_t ah[4], const uint32_t al[4],
                                     uint32_t bh0, uint32_t bh1,
                                     uint32_t bl0, uint32_t bl1) {
    mma_tf32(c, ah, bh0, bh1);
    mma_tf32(c, ah, bl0, bl1);
    mma_tf32(c, al, bh0, bh1);
}
__device__ __forceinline__ uint32_t fu(float x) { return __float_as_uint(x); }

__device__ __forceinline__ void cpa16(uint32_t saddr, const void* gptr) {
    asm volatile("cp.async.cg.shared.global [%0], [%1], 16;\n"
                 :: "r"(saddr), "l"(gptr));
}

// ---------------------------------------------------------------------------
// Pack kernel: dst[2i] = tf32_hi(src[i]), dst[2i+1] = tf32_lo(src[i])
// ---------------------------------------------------------------------------
__global__ void pack_split_kernel(const float* __restrict__ src,
                                  float* __restrict__ dst, int npairs)
{
    int i = blockIdx.x * blockDim.x + threadIdx.x;
    if (i < npairs) {
        float2 s = ((const float2*)src)[i];
        uint32_t h0, l0, h1, l1;
        split_tf32(s.x, h0, l0);
        split_tf32(s.y, h1, l1);
        ((float4*)dst)[i] = make_float4(__uint_as_float(h0), __uint_as_float(l0),
                                        __uint_as_float(h1), __uint_as_float(l1));
    }
}

// ---------------------------------------------------------------------------
// Pre-split tensor-core GEMM: C = A[M,K] @ W[Nc,K]^T + bias
// A2/W2 are packed (hi,lo): [rows][2K]. No cvt in the main loop.
// Block 128x128, 256 threads = 8 warps (4 M x 2 N), kb chunk = 32 k.
// SPLITOUT=1: C packed [M][2Nc]; SPLITOUT=0: plain float C[M][Nc].
// ---------------------------------------------------------------------------
#define GSTR 68   // smem row stride in floats (64 payload + 4 pad)

template<int SPLITOUT>
__global__ __launch_bounds__(256) void gemm2_kernel(
    const float* __restrict__ A2, const float* __restrict__ W2,
    const float* __restrict__ bias, float* __restrict__ C,
    int M, int Nc, int K)
{
    extern __shared__ float smg[];
    float* As2 = smg;                 // [128][GSTR]
    float* Ws2 = smg + 128 * GSTR;    // [128][GSTR]

    const int tid  = threadIdx.x;
    const int lane = tid & 31, warp = tid >> 5;
    const int g    = lane >> 2, tg = lane & 3;
    const int wm   = (warp >> 1) * 32;
    const int wn   = (warp & 1) * 64;
    const int mb   = blockIdx.y * 128, nb = blockIdx.x * 128;
    const int K2   = 2 * K;

    float acc[2][8][4];
    #pragma unroll
    for (int i = 0; i < 2; i++)
        #pragma unroll
        for (int j = 0; j < 8; j++)
            #pragma unroll
            for (int l = 0; l < 4; l++) acc[i][j][l] = 0.f;

    for (int kb = 0; kb < K; kb += 32) {
        #pragma unroll
        for (int l = tid; l < 128 * 16; l += 256) {
            int r = l >> 4, c4 = (l & 15) * 4;
            *(float4*)&As2[r * GSTR + c4] =
                *(const float4*)&A2[(size_t)(mb + r) * K2 + 2 * kb + c4];
        }
        #pragma unroll
        for (int l = tid; l < 128 * 16; l += 256) {
            int r = l >> 4, c4 = (l & 15) * 4;
            *(float4*)&Ws2[r * GSTR + c4] =
                *(const float4*)&W2[(size_t)(nb + r) * K2 + 2 * kb + c4];
        }
        __syncthreads();

        #pragma unroll
        for (int s = 0; s < 4; s++) {
            const int k8 = 8 * s;
            uint32_t ahi[2][4], alo[2][4];
            #pragma unroll
            for (int mi = 0; mi < 2; mi++) {
                const float* r0 = &As2[(wm + mi * 16 + g) * GSTR];
                const float* r1 = r0 + 8 * GSTR;
                float2 e0 = *(const float2*)&r0[2 * (k8 + tg)];
                float2 e1 = *(const float2*)&r1[2 * (k8 + tg)];
                float2 e2 = *(const float2*)&r0[2 * (k8 + tg + 4)];
                float2 e3 = *(const float2*)&r1[2 * (k8 + tg + 4)];
                ahi[mi][0] = fu(e0.x); alo[mi][0] = fu(e0.y);
                ahi[mi][1] = fu(e1.x); alo[mi][1] = fu(e1.y);
                ahi[mi][2] = fu(e2.x); alo[mi][2] = fu(e2.y);
                ahi[mi][3] = fu(e3.x); alo[mi][3] = fu(e3.y);
            }
            #pragma unroll
            for (int nj = 0; nj < 8; nj++) {
                const float* wr = &Ws2[(wn + nj * 8 + g) * GSTR];
                float2 b0 = *(const float2*)&wr[2 * (k8 + tg)];
                float2 b1 = *(const float2*)&wr[2 * (k8 + tg + 4)];
                #pragma unroll
                for (int mi = 0; mi < 2; mi++)
                    mma3(acc[mi][nj], ahi[mi], alo[mi],
                         fu(b0.x), fu(b1.x), fu(b0.y), fu(b1.y));
            }
        }
        __syncthreads();
    }

    #pragma unroll
    for (int mi = 0; mi < 2; mi++) {
        int r0 = mb + wm + mi * 16 + g;
        #pragma unroll
        for (int nj = 0; nj < 8; nj++) {
            int c0 = nb + wn + nj * 8 + 2 * tg;
            float bia0 = bias[c0], bia1 = bias[c0 + 1];
            float v00 = acc[mi][nj][0] + bia0;
            float v01 = acc[mi][nj][1] + bia1;
            float v10 = acc[mi][nj][2] + bia0;
            float v11 = acc[mi][nj][3] + bia1;
            if (SPLITOUT) {
                uint32_t h0, l0, h1, l1;
                split_tf32(v00, h0, l0); split_tf32(v01, h1, l1);
                *(float4*)&C[(size_t)r0 * 2 * Nc + 2 * c0] =
                    make_float4(__uint_as_float(h0), __uint_as_float(l0),
                                __uint_as_float(h1), __uint_as_float(l1));
                split_tf32(v10, h0, l0); split_tf32(v11, h1, l1);
                *(float4*)&C[(size_t)(r0 + 8) * 2 * Nc + 2 * c0] =
                    make_float4(__uint_as_float(h0), __uint_as_float(l0),
                                __uint_as_float(h1), __uint_as_float(l1));
            } else {
                C[(size_t)r0 * Nc + c0    ]       = v00;
                C[(size_t)r0 * Nc + c0 + 1]       = v01;
                C[(size_t)(r0 + 8) * Nc + c0    ] = v10;
                C[(size_t)(r0 + 8) * Nc + c0 + 1] = v11;
            }
        }
    }
}

// ---------------------------------------------------------------------------
// Attention: 128 threads / 4 warps, 64 queries per block.
// Each warp owns 16 query rows x ALL 32 keys, so S->P->PV stays in-warp
// (shuffle transform instead of P smem round trip).
// Q fragments in registers (loaded once). K/V double-buffered via cp.async.
// Output ctx written pre-split (packed) for the O projection.
// ---------------------------------------------------------------------------
#define KVSTR 132                 // smem row stride (128 payload + 4 pad)
#define KVROW (32*KVSTR)          // one K or V tile = 4224 floats
#define NTILES (N_/32)            // 32 key tiles

__global__ __launch_bounds__(128, 3) void attn_f_kernel(
    const float* __restrict__ q2, const float* __restrict__ k2,
    const float* __restrict__ v2, float* __restrict__ ctx2)
{
    extern __shared__ float sm[];
    // layout: K[0], K[1], V[0], V[1]
    float* Kb[2] = { sm,             sm + KVROW };
    float* Vb[2] = { sm + 2*KVROW,   sm + 3*KVROW };

    const int tid  = threadIdx.x;
    const int lane = tid & 31, warp = tid >> 5;
    const int g    = lane >> 2, tg = lane & 3;
    const int wm   = warp * 16;

    const int hidx = blockIdx.y;
    const int h    = hidx & (H_ - 1);
    const int tb   = hidx >> 3;
    const size_t base2 = (size_t)tb * N_ * D2_ + (size_t)h * (2 * HD_);
    const int q0   = blockIdx.x * 64;

    // ---- issue first two K/V tile loads (cp.async) ----
    auto load_tile = [&](int t, int buf) {
        const int k0 = 32 * t;
        #pragma unroll
        for (int l = tid; l < 32 * 32; l += 128) {
            int r = l >> 5, c4 = (l & 31) * 4;
            uint32_t kd = (uint32_t)__cvta_generic_to_shared(&Kb[buf][r * KVSTR + c4]);
            uint32_t vd = (uint32_t)__cvta_generic_to_shared(&Vb[buf][r * KVSTR + c4]);
            cpa16(kd, &k2[base2 + (size_t)(k0 + r) * D2_ + c4]);
            cpa16(vd, &v2[base2 + (size_t)(k0 + r) * D2_ + c4]);
        }
    };
    load_tile(0, 0);
    asm volatile("cp.async.commit_group;\n" ::: "memory");
    load_tile(1, 1);
    asm volatile("cp.async.commit_group;\n" ::: "memory");

    // ---- Q fragments -> registers (reused across all key tiles) ----
    uint32_t qh[8][4], ql[8][4];
    {
        const float* r0p = &q2[base2 + (size_t)(q0 + wm + g) * D2_];
        const float* r1p = r0p + (size_t)8 * D2_;
        #pragma unroll
        for (int s = 0; s < 8; s++) {
            float2 e0 = *(const float2*)&r0p[2 * (8 * s + tg)];
            float2 e1 = *(const float2*)&r1p[2 * (8 * s + tg)];
            float2 e2 = *(const float2*)&r0p[2 * (8 * s + tg + 4)];
            float2 e3 = *(const float2*)&r1p[2 * (8 * s + tg + 4)];
            qh[s][0] = fu(e0.x); ql[s][0] = fu(e0.y);
            qh[s][1] = fu(e1.x); ql[s][1] = fu(e1.y);
            qh[s][2] = fu(e2.x); ql[s][2] = fu(e2.y);
            qh[s][3] = fu(e3.x); ql[s][3] = fu(e3.y);
        }
    }

    float accPV[8][4];
    #pragma unroll
    for (int j = 0; j < 8; j++)
        #pragma unroll
        for (int l = 0; l < 4; l++) accPV[j][l] = 0.f;
    float dA = 0.f, dB = 0.f;

    const uint32_t srcA = (lane & ~3u) | (tg >> 1);
    const uint32_t srcB = srcA | 2u;

    for (int t = 0; t < NTILES; t++) {
        const int buf = t & 1;
        asm volatile("cp.async.wait_group 1;\n" ::: "memory");
        __syncthreads();

        const float* Kt = Kb[buf];
        const float* Vt = Vb[buf];

        // ---- S = Q K^T : 16 rows x 32 keys per warp ----
        float accS[4][4];
        #pragma unroll
        for (int j = 0; j < 4; j++)
            #pragma unroll
            for (int l = 0; l < 4; l++) accS[j][l] = 0.f;

        #pragma unroll
        for (int s = 0; s < 8; s++) {
            #pragma unroll
            for (int nj = 0; nj < 4; nj++) {
                const float* kr = &Kt[(8 * nj + g) * KVSTR];
                float2 b0 = *(const float2*)&kr[2 * (8 * s + tg)];
                float2 b1 = *(const float2*)&kr[2 * (8 * s + tg + 4)];
                mma3(accS[nj], qh[s], ql[s],
                     fu(b0.x), fu(b1.x), fu(b0.y), fu(b1.y));
            }
        }

        // ---- P = relu(S/8); denom; in-warp transform; PV ----
        #pragma unroll
        for (int kb = 0; kb < 4; kb++) {
            float p0 = fmaxf(accS[kb][0] * 0.125f, 0.f);
            float p1 = fmaxf(accS[kb][1] * 0.125f, 0.f);
            float p2 = fmaxf(accS[kb][2] * 0.125f, 0.f);
            float p3 = fmaxf(accS[kb][3] * 0.125f, 0.f);
            dA += p0 + p1;
            dB += p2 + p3;

            // accumulator layout -> A-fragment layout (within warp)
            float v00 = __shfl_sync(0xffffffffu, p0, srcA);
            float v01 = __shfl_sync(0xffffffffu, p1, srcA);
            float v02 = __shfl_sync(0xffffffffu, p2, srcA);
            float v03 = __shfl_sync(0xffffffffu, p3, srcA);
            float v10 = __shfl_sync(0xffffffffu, p0, srcB);
            float v11 = __shfl_sync(0xffffffffu, p1, srcB);
            float v12 = __shfl_sync(0xffffffffu, p2, srcB);
            float v13 = __shfl_sync(0xffffffffu, p3, srcB);
            float a0 = (tg & 1) ? v01 : v00;   // P[g   ][8kb+tg]
            float a1 = (tg & 1) ? v03 : v02;   // P[g+8 ][8kb+tg]
            float a2 = (tg & 1) ? v11 : v10;   // P[g   ][8kb+tg+4]
            float a3 = (tg & 1) ? v13 : v12;   // P[g+8 ][8kb+tg+4]

            uint32_t ah[4], al[4];
            split_tf32(a0, ah[0], al[0]);
            split_tf32(a1, ah[1], al[1]);
            split_tf32(a2, ah[2], al[2]);
            split_tf32(a3, ah[3], al[3]);

            const float* vr0 = &Vt[(8 * kb + tg) * KVSTR];
            const float* vr1 = &Vt[(8 * kb + tg + 4) * KVSTR];
            #pragma unroll
            for (int nj = 0; nj < 8; nj++) {
                float2 b0 = *(const float2*)&vr0[2 * (8 * nj + g)];
                float2 b1 = *(const float2*)&vr1[2 * (8 * nj + g)];
                mma3(accPV[nj], ah, al,
                     fu(b0.x), fu(b1.x), fu(b0.y), fu(b1.y));
            }
        }
        __syncthreads();   // all warps done reading buf before refill

        if (t + 2 < NTILES) load_tile(t + 2, buf);
        asm volatile("cp.async.commit_group;\n" ::: "memory");
    }

    // ---- denominator reduce over the 4 tg lanes of each row group ----
    dA += __shfl_xor_sync(0xffffffffu, dA, 1);
    dA += __shfl_xor_sync(0xffffffffu, dA, 2);
    dB += __shfl_xor_sync(0xffffffffu, dB, 1);
    dB += __shfl_xor_sync(0xffffffffu, dB, 2);
    const float invA = 1.f / (dA + 1e-6f);
    const float invB = 1.f / (dB + 1e-6f);

    // ---- write ctx pre-split (packed) for the O projection ----
    const size_t rowA = base2 + (size_t)(q0 + wm + g) * D2_;
    const size_t rowB = rowA + (size_t)8 * D2_;
    #pragma unroll
    for (int nj = 0; nj < 8; nj++) {
        int col = 8 * nj + 2 * tg;
        uint32_t h0, l0, h1, l1;
        split_tf32(accPV[nj][0] * invA, h0, l0);
        split_tf32(accPV[nj][1] * invA, h1, l1);
        *(float4*)&ctx2[rowA + 2 * col] =
            make_float4(__uint_as_float(h0), __uint_as_float(l0),
                        __uint_as_float(h1), __uint_as_float(l1));
        split_tf32(accPV[nj][2] * invB, h0, l0);
        split_tf32(accPV[nj][3] * invB, h1, l1);
        *(float4*)&ctx2[rowB + 2 * col] =
            make_float4(__uint_as_float(h0), __uint_as_float(l0),
                        __uint_as_float(h1), __uint_as_float(l1));
    }
}

// ---------------------------------------------------------------------------
// Launcher. Input order: x, wq, bq, wk, bk, wv, bv, wo, bo
// ---------------------------------------------------------------------------
extern "C" void kernel_launch(void* const* d_in, const int* in_sizes, int n_in,
                              void* d_out, int out_size)
{
    const float* x  = (const float*)d_in[0];
    const float* wq = (const float*)d_in[1];
    const float* bq = (const float*)d_in[2];
    const float* wk = (const float*)d_in[3];
    const float* bk = (const float*)d_in[4];
    const float* wv = (const float*)d_in[5];
    const float* bv = (const float*)d_in[6];
    const float* wo = (const float*)d_in[7];
    const float* bo = (const float*)d_in[8];
    float* out = (float*)d_out;

    float *x2, *q2, *k2, *v2, *wq2, *wk2, *wv2, *wo2;
    cudaGetSymbolAddress((void**)&x2,  g_x2);
    cudaGetSymbolAddress((void**)&q2,  g_q2);
    cudaGetSymbolAddress((void**)&k2,  g_k2);
    cudaGetSymbolAddress((void**)&v2,  g_v2);
    cudaGetSymbolAddress((void**)&wq2, g_wq2);
    cudaGetSymbolAddress((void**)&wk2, g_wk2);
    cudaGetSymbolAddress((void**)&wv2, g_wv2);
    cudaGetSymbolAddress((void**)&wo2, g_wo2);

    const int gemm_smem = 2 * 128 * GSTR * (int)sizeof(float);   // 69,632 B
    const int attn_smem = 4 * KVROW * (int)sizeof(float);        // 67,584 B
    cudaFuncSetAttribute(gemm2_kernel<1>,
        cudaFuncAttributeMaxDynamicSharedMemorySize, gemm_smem);
    cudaFuncSetAttribute(gemm2_kernel<0>,
        cudaFuncAttributeMaxDynamicSharedMemorySize, gemm_smem);
    cudaFuncSetAttribute(attn_f_kernel,
        cudaFuncAttributeMaxDynamicSharedMemorySize, attn_smem);

    // ---- pack inputs to (hi,lo) tf32 planes ----
    {
        int npx = M_ * D_ / 2;                 // x pairs
        pack_split_kernel<<<(npx + 255) / 256, 256>>>(x, x2, npx);
        int npw = D_ * D_ / 2;                 // weight pairs
        pack_split_kernel<<<(npw + 255) / 256, 256>>>(wq, wq2, npw);
        pack_split_kernel<<<(npw + 255) / 256, 256>>>(wk, wk2, npw);
        pack_split_kernel<<<(npw + 255) / 256, 256>>>(wv, wv2, npw);
        pack_split_kernel<<<(npw + 255) / 256, 256>>>(wo, wo2, npw);
    }

    dim3 gProj(D_ / 128, M_ / 128);        // 4 x 128
    gemm2_kernel<1><<<gProj, 256, gemm_smem>>>(x2, wq2, bq, q2, M_, D_, D_);
    gemm2_kernel<1><<<gProj, 256, gemm_smem>>>(x2, wk2, bk, k2, M_, D_, D_);
    gemm2_kernel<1><<<gProj, 256, gemm_smem>>>(x2, wv2, bv, v2, M_, D_, D_);

    dim3 gAttn(N_ / 64, T_ * B_ * H_);     // 16 x 128
    // writes packed ctx into g_x2 (x2 no longer needed)
    attn_f_kernel<<<gAttn, 128, attn_smem>>>(q2, k2, v2, x2);

    gemm2_kernel<0><<<gProj, 256, gemm_smem>>>(x2, wo2, bo, out, M_, D_, D_);
}

// round 7
// speedup vs baseline: 2.7996x; 2.2361x over previous
#include <cuda_runtime.h>
#include <cuda_bf16.h>
#include <cstdint>

// Problem constants
#define T_  4
#define B_  4
#define N_  1024
#define D_  512
#define H_  8
#define HD_ 64
#define M_  (T_*B_*N_)     // 16384 rows
#define ROWU 512           // packed row width in u32: [hi 256][mid 256]

// Scratch (no cudaMalloc). Packed bf16 (hi,mid) plane buffers, u32 units.
__device__ uint32_t gU_x2 [(size_t)M_*ROWU];   // x packed; reused as ctx packed
__device__ uint32_t gU_q2 [(size_t)M_*ROWU];
__device__ uint32_t gU_k2 [(size_t)M_*ROWU];
__device__ uint32_t gU_v2 [(size_t)M_*ROWU];
__device__ uint32_t gU_v2t[(size_t)M_*ROWU];   // V transposed per head: [head][ch][hi 512|mid 512]
__device__ uint32_t gU_wq2[(size_t)D_*ROWU];
__device__ uint32_t gU_wk2[(size_t)D_*ROWU];
__device__ uint32_t gU_wv2[(size_t)D_*ROWU];
__device__ uint32_t gU_wo2[(size_t)D_*ROWU];

// ---------------------------------------------------------------------------
// bf16 split helpers
// ---------------------------------------------------------------------------
__device__ __forceinline__ uint32_t bpack(__nv_bfloat16 a, __nv_bfloat16 b) {
    return (uint32_t)__bfloat16_as_ushort(a) |
           ((uint32_t)__bfloat16_as_ushort(b) << 16);
}
// split two adjacent elements into packed hi-pair and mid-pair
__device__ __forceinline__ void split2(float x0, float x1,
                                       uint32_t& hi, uint32_t& mid) {
    __nv_bfloat16 h0 = __float2bfloat16(x0);
    __nv_bfloat16 h1 = __float2bfloat16(x1);
    __nv_bfloat16 m0 = __float2bfloat16(x0 - __bfloat162float(h0));
    __nv_bfloat16 m1 = __float2bfloat16(x1 - __bfloat162float(h1));
    hi = bpack(h0, h1); mid = bpack(m0, m1);
}
__device__ __forceinline__ void mma_bf16(float c[4], const uint32_t a[4],
                                         uint32_t b0, uint32_t b1) {
    asm volatile(
        "mma.sync.aligned.m16n8k16.row.col.f32.bf16.bf16.f32 "
        "{%0,%1,%2,%3}, {%4,%5,%6,%7}, {%8,%9}, {%0,%1,%2,%3};"
        : "+f"(c[0]), "+f"(c[1]), "+f"(c[2]), "+f"(c[3])
        : "r"(a[0]), "r"(a[1]), "r"(a[2]), "r"(a[3]), "r"(b0), "r"(b1));
}
// 3-term: C += Ah*Bh + Ah*Bm + Am*Bh
__device__ __forceinline__ void mma3b(float c[4],
                                      const uint32_t ah[4], const uint32_t am[4],
                                      uint32_t bh0, uint32_t bh1,
                                      uint32_t bm0, uint32_t bm1) {
    mma_bf16(c, ah, bh0, bh1);
    mma_bf16(c, ah, bm0, bm1);
    mma_bf16(c, am, bh0, bh1);
}
__device__ __forceinline__ void cpa16(uint32_t saddr, const void* gptr) {
    asm volatile("cp.async.cg.shared.global [%0], [%1], 16;\n"
                 :: "r"(saddr), "l"(gptr));
}
__device__ __forceinline__ uint32_t s2u(const void* p) {
    return (uint32_t)__cvta_generic_to_shared(p);
}

// ---------------------------------------------------------------------------
// Pack: fp32 rows of 512 -> packed planes [hi 256 u32][mid 256 u32]
// ---------------------------------------------------------------------------
__global__ void pack_planes_kernel(const float* __restrict__ src,
                                   uint32_t* __restrict__ dst, int total)
{
    int i = blockIdx.x * blockDim.x + threadIdx.x;   // pair index
    if (i < total) {
        float2 s = ((const float2*)src)[i];
        int r = i >> 8, c = i & 255;
        uint32_t hi, mid;
        split2(s.x, s.y, hi, mid);
        dst[(size_t)r * ROWU + c]       = hi;
        dst[(size_t)r * ROWU + 256 + c] = mid;
    }
}

// ---------------------------------------------------------------------------
// V transpose: v2 [tok][ch planes] -> v2t [head][ch][hi 512 | mid 512] (keys)
// Block 128 thr: one (head, 32-key group).
// ---------------------------------------------------------------------------
__global__ void transpose_v_kernel(const uint32_t* __restrict__ v2,
                                   uint32_t* __restrict__ v2t)
{
    __shared__ uint32_t ts[32][65];   // [tok][hi 32 u32 | mid 32 u32] padded

    const int head = blockIdx.x;            // tb*H + h
    const int h    = head & (H_ - 1);
    const int tb   = head >> 3;
    const int k0   = blockIdx.y * 32;
    const int tokb = tb * N_ + k0;

    for (int i = threadIdx.x; i < 32 * 64; i += 128) {
        int tok = i >> 6, c = i & 63;
        size_t src = (size_t)(tokb + tok) * ROWU + h * 32 +
                     (c < 32 ? c : 256 + (c - 32));
        ts[tok][c] = v2[src];
    }
    __syncthreads();

    const size_t outb = (size_t)head * (64 * 1024);
    for (int i = threadIdx.x; i < 64 * 32; i += 128) {
        int ch = i >> 5, rest = i & 31;
        int plane = rest >> 4, j = rest & 15;          // keys 2j,2j+1
        uint32_t w0 = ts[2 * j    ][plane * 32 + (ch >> 1)];
        uint32_t w1 = ts[2 * j + 1][plane * 32 + (ch >> 1)];
        uint16_t e0 = (ch & 1) ? (uint16_t)(w0 >> 16) : (uint16_t)(w0 & 0xffff);
        uint16_t e1 = (ch & 1) ? (uint16_t)(w1 >> 16) : (uint16_t)(w1 & 0xffff);
        v2t[outb + (size_t)ch * 1024 + plane * 512 + (k0 >> 1) + j] =
            (uint32_t)e0 | ((uint32_t)e1 << 16);
    }
}

// ---------------------------------------------------------------------------
// bf16-split GEMM: C = A[M,512] @ W[Nc,512]^T + bias. Double-buffered cp.async.
// Block 128x128, 256 thr (4Mx2N warps). Chunk 32k -> 2 x k16 MMA steps.
// Smem row per chunk: [hi 16 u32][mid 16 u32][pad 4] stride 36.
// ---------------------------------------------------------------------------
#define GSTR  36
#define GSTG  (128*GSTR)   // one stage, one matrix (u32)
#define NCHUNK 16

template<int SPLITOUT>
__global__ __launch_bounds__(256, 2) void gemm_bf16_kernel(
    const uint32_t* __restrict__ A2, const uint32_t* __restrict__ W2,
    const float* __restrict__ bias, void* __restrict__ Cout,
    int M, int Nc)
{
    extern __shared__ uint32_t smg[];
    uint32_t* Abuf[2] = { smg,            smg + GSTG };
    uint32_t* Wbuf[2] = { smg + 2*GSTG,   smg + 3*GSTG };

    const int tid  = threadIdx.x;
    const int lane = tid & 31, warp = tid >> 5;
    const int g    = lane >> 2, tg = lane & 3;
    const int wm   = (warp >> 1) * 32;
    const int wn   = (warp & 1) * 64;
    const int mb   = blockIdx.y * 128, nb = blockIdx.x * 128;

    auto load_stage = [&](int t, int buf) {
        #pragma unroll
        for (int l = tid; l < 1024; l += 256) {
            int r = l >> 3, part = l & 7;
            size_t src; uint32_t dst;
            if (part < 4) {
                src = (size_t)(mb + r) * ROWU + 16 * t + 4 * part;
                dst = s2u(&Abuf[buf][r * GSTR + 4 * part]);
            } else {
                src = (size_t)(mb + r) * ROWU + 256 + 16 * t + 4 * (part - 4);
                dst = s2u(&Abuf[buf][r * GSTR + 16 + 4 * (part - 4)]);
            }
            cpa16(dst, &A2[src]);
        }
        #pragma unroll
        for (int l = tid; l < 1024; l += 256) {
            int r = l >> 3, part = l & 7;
            size_t src; uint32_t dst;
            if (part < 4) {
                src = (size_t)(nb + r) * ROWU + 16 * t + 4 * part;
                dst = s2u(&Wbuf[buf][r * GSTR + 4 * part]);
            } else {
                src = (size_t)(nb + r) * ROWU + 256 + 16 * t + 4 * (part - 4);
                dst = s2u(&Wbuf[buf][r * GSTR + 16 + 4 * (part - 4)]);
            }
            cpa16(dst, &W2[src]);
        }
    };

    float acc[2][8][4];
    #pragma unroll
    for (int i = 0; i < 2; i++)
        #pragma unroll
        for (int j = 0; j < 8; j++)
            #pragma unroll
            for (int l = 0; l < 4; l++) acc[i][j][l] = 0.f;

    load_stage(0, 0);
    asm volatile("cp.async.commit_group;\n" ::: "memory");
    load_stage(1, 1);
    asm volatile("cp.async.commit_group;\n" ::: "memory");

    for (int t = 0; t < NCHUNK; t++) {
        const int buf = t & 1;
        asm volatile("cp.async.wait_group 1;\n" ::: "memory");
        __syncthreads();

        const uint32_t* At = Abuf[buf];
        const uint32_t* Wt = Wbuf[buf];

        #pragma unroll
        for (int s = 0; s < 2; s++) {
            uint32_t ah[2][4], am[2][4];
            #pragma unroll
            for (int mi = 0; mi < 2; mi++) {
                const uint32_t* r0 = &At[(wm + 16 * mi + g) * GSTR];
                const uint32_t* r1 = r0 + 8 * GSTR;
                ah[mi][0] = r0[8*s + tg];      ah[mi][1] = r1[8*s + tg];
                ah[mi][2] = r0[8*s + tg + 4];  ah[mi][3] = r1[8*s + tg + 4];
                am[mi][0] = r0[16 + 8*s + tg];     am[mi][1] = r1[16 + 8*s + tg];
                am[mi][2] = r0[16 + 8*s + tg + 4]; am[mi][3] = r1[16 + 8*s + tg + 4];
            }
            #pragma unroll
            for (int nj = 0; nj < 8; nj++) {
                const uint32_t* wr = &Wt[(wn + 8 * nj + g) * GSTR];
                uint32_t bh0 = wr[8*s + tg],      bh1 = wr[8*s + tg + 4];
                uint32_t bm0 = wr[16 + 8*s + tg], bm1 = wr[16 + 8*s + tg + 4];
                mma3b(acc[0][nj], ah[0], am[0], bh0, bh1, bm0, bm1);
                mma3b(acc[1][nj], ah[1], am[1], bh0, bh1, bm0, bm1);
            }
        }
        __syncthreads();

        if (t + 2 < NCHUNK) load_stage(t + 2, buf);
        asm volatile("cp.async.commit_group;\n" ::: "memory");
    }

    #pragma unroll
    for (int mi = 0; mi < 2; mi++) {
        int r0 = mb + wm + mi * 16 + g;
        #pragma unroll
        for (int nj = 0; nj < 8; nj++) {
            int c0 = nb + wn + nj * 8 + 2 * tg;
            float bia0 = bias[c0], bia1 = bias[c0 + 1];
            float v00 = acc[mi][nj][0] + bia0;
            float v01 = acc[mi][nj][1] + bia1;
            float v10 = acc[mi][nj][2] + bia0;
            float v11 = acc[mi][nj][3] + bia1;
            if (SPLITOUT) {
                uint32_t* C = (uint32_t*)Cout;
                uint32_t hi, mid;
                split2(v00, v01, hi, mid);
                C[(size_t)r0 * ROWU + (c0 >> 1)]       = hi;
                C[(size_t)r0 * ROWU + 256 + (c0 >> 1)] = mid;
                split2(v10, v11, hi, mid);
                C[(size_t)(r0 + 8) * ROWU + (c0 >> 1)]       = hi;
                C[(size_t)(r0 + 8) * ROWU + 256 + (c0 >> 1)] = mid;
            } else {
                float* C = (float*)Cout;
                *(float2*)&C[(size_t)r0 * Nc + c0]       = make_float2(v00, v01);
                *(float2*)&C[(size_t)(r0 + 8) * Nc + c0] = make_float2(v10, v11);
            }
        }
    }
}

// ---------------------------------------------------------------------------
// bf16-split attention. 128 thr / 4 warps; warp owns 16 q-rows x all 32 keys.
// k16 fragment layout == pair of k8 accumulator layouts -> S->P->PV in-lane
// (no shuffles). K row-major, V transposed (v2t). cp.async double buffered.
// ---------------------------------------------------------------------------
#define KSTR 68                 // K smem row: [hi 32 u32][mid 32][pad 4]
#define VSTR 36                 // Vt smem row: [hi 16 u32][mid 16][pad 4]
#define KTILE (32*KSTR)         // 2176 u32
#define VTILE (64*VSTR)         // 2304 u32
#define NTILES (N_/32)

__global__ __launch_bounds__(128, 4) void attn_bf16_kernel(
    const uint32_t* __restrict__ q2, const uint32_t* __restrict__ k2,
    const uint32_t* __restrict__ v2t, uint32_t* __restrict__ ctx2)
{
    extern __shared__ uint32_t sma[];
    uint32_t* Kb[2] = { sma,             sma + KTILE };
    uint32_t* Vb[2] = { sma + 2*KTILE,   sma + 2*KTILE + VTILE };

    const int tid  = threadIdx.x;
    const int lane = tid & 31, warp = tid >> 5;
    const int g    = lane >> 2, tg = lane & 3;
    const int wm   = warp * 16;

    const int hidx = blockIdx.y;
    const int h    = hidx & (H_ - 1);
    const int tb   = hidx >> 3;
    const int tokb = tb * N_;
    const size_t headv = (size_t)hidx * (64 * 1024);
    const int q0   = blockIdx.x * 64;

    auto load_tile = [&](int t, int buf) {
        const int k0 = 32 * t;
        #pragma unroll
        for (int l = tid; l < 512; l += 128) {   // K: 32 keys x 64 u32
            int key = l >> 4, part = l & 15;
            size_t rowb = (size_t)(tokb + k0 + key) * ROWU + h * 32;
            size_t src; uint32_t dst;
            if (part < 8) {
                src = rowb + 4 * part;
                dst = s2u(&Kb[buf][key * KSTR + 4 * part]);
            } else {
                src = rowb + 256 + 4 * (part - 8);
                dst = s2u(&Kb[buf][key * KSTR + 32 + 4 * (part - 8)]);
            }
            cpa16(dst, &k2[src]);
        }
        #pragma unroll
        for (int l = tid; l < 512; l += 128) {   // Vt: 64 ch x 32 u32
            int ch = l >> 3, part = l & 7;
            size_t vrow = headv + (size_t)ch * 1024;
            size_t src; uint32_t dst;
            if (part < 4) {
                src = vrow + (k0 >> 1) + 4 * part;
                dst = s2u(&Vb[buf][ch * VSTR + 4 * part]);
            } else {
                src = vrow + 512 + (k0 >> 1) + 4 * (part - 4);
                dst = s2u(&Vb[buf][ch * VSTR + 16 + 4 * (part - 4)]);
            }
            cpa16(dst, &v2t[src]);
        }
    };

    load_tile(0, 0);
    asm volatile("cp.async.commit_group;\n" ::: "memory");
    load_tile(1, 1);
    asm volatile("cp.async.commit_group;\n" ::: "memory");

    // ---- Q fragments -> registers (4 k16 steps over HD=64) ----
    uint32_t qh[4][4], qm[4][4];
    {
        size_t rA = (size_t)(tokb + q0 + wm + g) * ROWU + h * 32;
        size_t rB = rA + (size_t)8 * ROWU;
        #pragma unroll
        for (int s = 0; s < 4; s++) {
            qh[s][0] = q2[rA + 8*s + tg];        qh[s][1] = q2[rB + 8*s + tg];
            qh[s][2] = q2[rA + 8*s + tg + 4];    qh[s][3] = q2[rB + 8*s + tg + 4];
            qm[s][0] = q2[rA + 256 + 8*s + tg];      qm[s][1] = q2[rB + 256 + 8*s + tg];
            qm[s][2] = q2[rA + 256 + 8*s + tg + 4];  qm[s][3] = q2[rB + 256 + 8*s + tg + 4];
        }
    }

    float accPV[8][4];
    #pragma unroll
    for (int j = 0; j < 8; j++)
        #pragma unroll
        for (int l = 0; l < 4; l++) accPV[j][l] = 0.f;
    float dA = 0.f, dB = 0.f;

    for (int t = 0; t < NTILES; t++) {
        const int buf = t & 1;
        asm volatile("cp.async.wait_group 1;\n" ::: "memory");
        __syncthreads();

        const uint32_t* Kt = Kb[buf];
        const uint32_t* Vt = Vb[buf];

        // ---- S = Q K^T : 16 rows x 32 keys ----
        float accS[4][4];
        #pragma unroll
        for (int j = 0; j < 4; j++)
            #pragma unroll
            for (int l = 0; l < 4; l++) accS[j][l] = 0.f;

        #pragma unroll
        for (int s = 0; s < 4; s++) {
            #pragma unroll
            for (int nj = 0; nj < 4; nj++) {
                const uint32_t* kr = &Kt[(8 * nj + g) * KSTR];
                uint32_t bh0 = kr[8*s + tg],      bh1 = kr[8*s + tg + 4];
                uint32_t bm0 = kr[32 + 8*s + tg], bm1 = kr[32 + 8*s + tg + 4];
                mma3b(accS[nj], qh[s], qm[s], bh0, bh1, bm0, bm1);
            }
        }

        // ---- P = relu(S/8) in-lane -> A frags; denom; PV ----
        #pragma unroll
        for (int kb = 0; kb < 2; kb++) {
            float p0 = fmaxf(accS[2*kb    ][0] * 0.125f, 0.f);
            float p1 = fmaxf(accS[2*kb    ][1] * 0.125f, 0.f);
            float p2 = fmaxf(accS[2*kb    ][2] * 0.125f, 0.f);
            float p3 = fmaxf(accS[2*kb    ][3] * 0.125f, 0.f);
            float p4 = fmaxf(accS[2*kb + 1][0] * 0.125f, 0.f);
            float p5 = fmaxf(accS[2*kb + 1][1] * 0.125f, 0.f);
            float p6 = fmaxf(accS[2*kb + 1][2] * 0.125f, 0.f);
            float p7 = fmaxf(accS[2*kb + 1][3] * 0.125f, 0.f);
            dA += p0 + p1 + p4 + p5;
            dB += p2 + p3 + p6 + p7;

            uint32_t ah[4], am[4];
            split2(p0, p1, ah[0], am[0]);   // row g,   keys 16kb+2tg..
            split2(p2, p3, ah[1], am[1]);   // row g+8
            split2(p4, p5, ah[2], am[2]);   // row g,   keys 16kb+8+2tg..
            split2(p6, p7, ah[3], am[3]);   // row g+8

            #pragma unroll
            for (int nj = 0; nj < 8; nj++) {
                const uint32_t* vr = &Vt[(8 * nj + g) * VSTR];
                uint32_t bh0 = vr[8*kb + tg],      bh1 = vr[8*kb + tg + 4];
                uint32_t bm0 = vr[16 + 8*kb + tg], bm1 = vr[16 + 8*kb + tg + 4];
                mma3b(accPV[nj], ah, am, bh0, bh1, bm0, bm1);
            }
        }
        __syncthreads();

        if (t + 2 < NTILES) load_tile(t + 2, buf);
        asm volatile("cp.async.commit_group;\n" ::: "memory");
    }

    // ---- denominator reduce over tg lanes ----
    dA += __shfl_xor_sync(0xffffffffu, dA, 1);
    dA += __shfl_xor_sync(0xffffffffu, dA, 2);
    dB += __shfl_xor_sync(0xffffffffu, dB, 1);
    dB += __shfl_xor_sync(0xffffffffu, dB, 2);
    const float invA = 1.f / (dA + 1e-6f);
    const float invB = 1.f / (dB + 1e-6f);

    // ---- write ctx packed (planes) for O projection ----
    size_t rA = (size_t)(tokb + q0 + wm + g) * ROWU + h * 32;
    size_t rB = rA + (size_t)8 * ROWU;
    #pragma unroll
    for (int nj = 0; nj < 8; nj++) {
        uint32_t hi, mid;
        split2(accPV[nj][0] * invA, accPV[nj][1] * invA, hi, mid);
        ctx2[rA + 4*nj + tg]       = hi;
        ctx2[rA + 256 + 4*nj + tg] = mid;
        split2(accPV[nj][2] * invB, accPV[nj][3] * invB, hi, mid);
        ctx2[rB + 4*nj + tg]       = hi;
        ctx2[rB + 256 + 4*nj + tg] = mid;
    }
}

// ---------------------------------------------------------------------------
// Launcher. Input order: x, wq, bq, wk, bk, wv, bv, wo, bo
// ---------------------------------------------------------------------------
extern "C" void kernel_launch(void* const* d_in, const int* in_sizes, int n_in,
                              void* d_out, int out_size)
{
    const float* x  = (const float*)d_in[0];
    const float* wq = (const float*)d_in[1];
    const float* bq = (const float*)d_in[2];
    const float* wk = (const float*)d_in[3];
    const float* bk = (const float*)d_in[4];
    const float* wv = (const float*)d_in[5];
    const float* bv = (const float*)d_in[6];
    const float* wo = (const float*)d_in[7];
    const float* bo = (const float*)d_in[8];
    float* out = (float*)d_out;

    uint32_t *x2, *q2, *k2, *v2, *v2t, *wq2, *wk2, *wv2, *wo2;
    cudaGetSymbolAddress((void**)&x2,  gU_x2);
    cudaGetSymbolAddress((void**)&q2,  gU_q2);
    cudaGetSymbolAddress((void**)&k2,  gU_k2);
    cudaGetSymbolAddress((void**)&v2,  gU_v2);
    cudaGetSymbolAddress((void**)&v2t, gU_v2t);
    cudaGetSymbolAddress((void**)&wq2, gU_wq2);
    cudaGetSymbolAddress((void**)&wk2, gU_wk2);
    cudaGetSymbolAddress((void**)&wv2, gU_wv2);
    cudaGetSymbolAddress((void**)&wo2, gU_wo2);

    const int gemm_smem = 4 * GSTG * (int)sizeof(uint32_t);            // 73,728 B
    const int attn_smem = (2*KTILE + 2*VTILE) * (int)sizeof(uint32_t); // 35,840 B
    cudaFuncSetAttribute(gemm_bf16_kernel<1>,
        cudaFuncAttributeMaxDynamicSharedMemorySize, gemm_smem);
    cudaFuncSetAttribute(gemm_bf16_kernel<0>,
        cudaFuncAttributeMaxDynamicSharedMemorySize, gemm_smem);
    cudaFuncSetAttribute(attn_bf16_kernel,
        cudaFuncAttributeMaxDynamicSharedMemorySize, attn_smem);

    // ---- pack fp32 -> bf16 (hi,mid) planes ----
    {
        int npx = M_ * 256;                       // pairs in x
        pack_planes_kernel<<<(npx + 255) / 256, 256>>>(x, x2, npx);
        int npw = D_ * 256;
        pack_planes_kernel<<<(npw + 255) / 256, 256>>>(wq, wq2, npw);
        pack_planes_kernel<<<(npw + 255) / 256, 256>>>(wk, wk2, npw);
        pack_planes_kernel<<<(npw + 255) / 256, 256>>>(wv, wv2, npw);
        pack_planes_kernel<<<(npw + 255) / 256, 256>>>(wo, wo2, npw);
    }

    dim3 gProj(D_ / 128, M_ / 128);        // 4 x 128
    gemm_bf16_kernel<1><<<gProj, 256, gemm_smem>>>(x2, wq2, bq, q2, M_, D_);
    gemm_bf16_kernel<1><<<gProj, 256, gemm_smem>>>(x2, wk2, bk, k2, M_, D_);
    gemm_bf16_kernel<1><<<gProj, 256, gemm_smem>>>(x2, wv2, bv, v2, M_, D_);

    dim3 gT(T_ * B_ * H_, N_ / 32);        // 128 x 32
    transpose_v_kernel<<<gT, 128>>>(v2, v2t);

    dim3 gAttn(N_ / 64, T_ * B_ * H_);     // 16 x 128
    attn_bf16_kernel<<<gAttn, 128, attn_smem>>>(q2, k2, v2t, x2);  // ctx -> x2

    gemm_bf16_kernel<0><<<gProj, 256, gemm_smem>>>(x2, wo2, bo, out, M_, D_);
}

// round 9
// speedup vs baseline: 3.3733x; 1.2049x over previous
#include <cuda_runtime.h>
#include <cuda_bf16.h>
#include <cstdint>

// Problem constants
#define T_  4
#define B_  4
#define N_  1024
#define D_  512
#define H_  8
#define HD_ 64
#define M_  (T_*B_*N_)     // 16384 rows
#define ROWU 512           // packed row width in u32: [hi 256][mid 256]

// Scratch (no cudaMalloc). Packed bf16 (hi,mid) plane buffers, u32 units.
__device__ uint32_t gU_x2 [(size_t)M_*ROWU];   // x packed; reused as ctx packed
__device__ uint32_t gU_q2 [(size_t)M_*ROWU];
__device__ uint32_t gU_k2 [(size_t)M_*ROWU];
__device__ uint32_t gU_v2 [(size_t)M_*ROWU];
__device__ uint32_t gU_v2t[(size_t)M_*ROWU];   // V transposed per head
__device__ uint32_t gU_wq2[(size_t)D_*ROWU];
__device__ uint32_t gU_wk2[(size_t)D_*ROWU];
__device__ uint32_t gU_wv2[(size_t)D_*ROWU];
__device__ uint32_t gU_wo2[(size_t)D_*ROWU];

// ---------------------------------------------------------------------------
// bf16 split + mma + ldmatrix helpers
// ---------------------------------------------------------------------------
__device__ __forceinline__ uint32_t bpack(__nv_bfloat16 a, __nv_bfloat16 b) {
    return (uint32_t)__bfloat16_as_ushort(a) |
           ((uint32_t)__bfloat16_as_ushort(b) << 16);
}
__device__ __forceinline__ void split2(float x0, float x1,
                                       uint32_t& hi, uint32_t& mid) {
    __nv_bfloat16 h0 = __float2bfloat16(x0);
    __nv_bfloat16 h1 = __float2bfloat16(x1);
    __nv_bfloat16 m0 = __float2bfloat16(x0 - __bfloat162float(h0));
    __nv_bfloat16 m1 = __float2bfloat16(x1 - __bfloat162float(h1));
    hi = bpack(h0, h1); mid = bpack(m0, m1);
}
__device__ __forceinline__ void mma_bf16(float c[4], const uint32_t a[4],
                                         uint32_t b0, uint32_t b1) {
    asm volatile(
        "mma.sync.aligned.m16n8k16.row.col.f32.bf16.bf16.f32 "
        "{%0,%1,%2,%3}, {%4,%5,%6,%7}, {%8,%9}, {%0,%1,%2,%3};"
        : "+f"(c[0]), "+f"(c[1]), "+f"(c[2]), "+f"(c[3])
        : "r"(a[0]), "r"(a[1]), "r"(a[2]), "r"(a[3]), "r"(b0), "r"(b1));
}
__device__ __forceinline__ void mma3b(float c[4],
                                      const uint32_t ah[4], const uint32_t am[4],
                                      uint32_t bh0, uint32_t bh1,
                                      uint32_t bm0, uint32_t bm1) {
    mma_bf16(c, ah, bh0, bh1);
    mma_bf16(c, ah, bm0, bm1);
    mma_bf16(c, am, bh0, bh1);
}
__device__ __forceinline__ void ldm_x4(uint32_t& r0, uint32_t& r1,
                                       uint32_t& r2, uint32_t& r3, uint32_t addr) {
    asm volatile("ldmatrix.sync.aligned.m8n8.x4.shared.b16 {%0,%1,%2,%3}, [%4];"
                 : "=r"(r0), "=r"(r1), "=r"(r2), "=r"(r3) : "r"(addr));
}
__device__ __forceinline__ void cpa16(uint32_t saddr, const void* gptr) {
    asm volatile("cp.async.cg.shared.global [%0], [%1], 16;\n"
                 :: "r"(saddr), "l"(gptr));
}
__device__ __forceinline__ uint32_t s2u(const void* p) {
    return (uint32_t)__cvta_generic_to_shared(p);
}

// ---------------------------------------------------------------------------
// Pack: fp32 rows of 512 -> packed planes [hi 256 u32][mid 256 u32]
// ---------------------------------------------------------------------------
__global__ void pack_planes_kernel(const float* __restrict__ src,
                                   uint32_t* __restrict__ dst, int total)
{
    int i = blockIdx.x * blockDim.x + threadIdx.x;
    if (i < total) {
        float2 s = ((const float2*)src)[i];
        int r = i >> 8, c = i & 255;
        uint32_t hi, mid;
        split2(s.x, s.y, hi, mid);
        dst[(size_t)r * ROWU + c]       = hi;
        dst[(size_t)r * ROWU + 256 + c] = mid;
    }
}

// ---------------------------------------------------------------------------
// V transpose: v2 [tok][ch planes] -> v2t [head][ch][hi 512 | mid 512]
// ---------------------------------------------------------------------------
__global__ void transpose_v_kernel(const uint32_t* __restrict__ v2,
                                   uint32_t* __restrict__ v2t)
{
    __shared__ uint32_t ts[32][65];

    const int head = blockIdx.x;
    const int h    = head & (H_ - 1);
    const int tb   = head >> 3;
    const int k0   = blockIdx.y * 32;
    const int tokb = tb * N_ + k0;

    for (int i = threadIdx.x; i < 32 * 64; i += 128) {
        int tok = i >> 6, c = i & 63;
        size_t src = (size_t)(tokb + tok) * ROWU + h * 32 +
                     (c < 32 ? c : 256 + (c - 32));
        ts[tok][c] = v2[src];
    }
    __syncthreads();

    const size_t outb = (size_t)head * (64 * 1024);
    for (int i = threadIdx.x; i < 64 * 32; i += 128) {
        int ch = i >> 5, rest = i & 31;
        int plane = rest >> 4, j = rest & 15;
        uint32_t w0 = ts[2 * j    ][plane * 32 + (ch >> 1)];
        uint32_t w1 = ts[2 * j + 1][plane * 32 + (ch >> 1)];
        uint16_t e0 = (ch & 1) ? (uint16_t)(w0 >> 16) : (uint16_t)(w0 & 0xffff);
        uint16_t e1 = (ch & 1) ? (uint16_t)(w1 >> 16) : (uint16_t)(w1 & 0xffff);
        v2t[outb + (size_t)ch * 1024 + plane * 512 + (k0 >> 1) + j] =
            (uint32_t)e0 | ((uint32_t)e1 << 16);
    }
}

// ---------------------------------------------------------------------------
// bf16-split GEMM with ldmatrix operand fetch. Double-buffered cp.async.
// Block 128x128, 256 thr (4Mx2N warps). Chunk 32k -> 2 x k16 steps.
// Smem row per chunk: [hi 16 u32][mid 16 u32][pad 4] stride 36.
// ---------------------------------------------------------------------------
#define GSTR  36
#define GSTG  (128*GSTR)
#define NCHUNK 16

template<int SPLITOUT>
__global__ __launch_bounds__(256, 2) void gemm_bf16_kernel(
    const uint32_t* __restrict__ A2, const uint32_t* __restrict__ W2,
    const float* __restrict__ bias, void* __restrict__ Cout,
    int M, int Nc)
{
    extern __shared__ uint32_t smg[];
    uint32_t* Abuf[2] = { smg,            smg + GSTG };
    uint32_t* Wbuf[2] = { smg + 2*GSTG,   smg + 3*GSTG };

    const int tid  = threadIdx.x;
    const int lane = tid & 31, warp = tid >> 5;
    const int g    = lane >> 2, tg = lane & 3;
    const int wm   = (warp >> 1) * 32;
    const int wn   = (warp & 1) * 64;
    const int mb   = blockIdx.y * 128, nb = blockIdx.x * 128;

    // ldmatrix per-lane offsets (u32 units, relative to buffer start)
    const uint32_t aOff = (uint32_t)((wm + (lane & 15)) * GSTR + (lane >> 4) * 4);
    const uint32_t wOff = (uint32_t)((wn + (lane & 7)) * GSTR +
                                     ((lane >> 3) & 1) * 4 +
                                     (lane >> 4) * 8 * GSTR);

    auto load_stage = [&](int t, int buf) {
        #pragma unroll
        for (int l = tid; l < 1024; l += 256) {
            int r = l >> 3, part = l & 7;
            size_t src; uint32_t dst;
            if (part < 4) {
                src = (size_t)(mb + r) * ROWU + 16 * t + 4 * part;
                dst = s2u(&Abuf[buf][r * GSTR + 4 * part]);
            } else {
                src = (size_t)(mb + r) * ROWU + 256 + 16 * t + 4 * (part - 4);
                dst = s2u(&Abuf[buf][r * GSTR + 16 + 4 * (part - 4)]);
            }
            cpa16(dst, &A2[src]);
        }
        #pragma unroll
        for (int l = tid; l < 1024; l += 256) {
            int r = l >> 3, part = l & 7;
            size_t src; uint32_t dst;
            if (part < 4) {
                src = (size_t)(nb + r) * ROWU + 16 * t + 4 * part;
                dst = s2u(&Wbuf[buf][r * GSTR + 4 * part]);
            } else {
                src = (size_t)(nb + r) * ROWU + 256 + 16 * t + 4 * (part - 4);
                dst = s2u(&Wbuf[buf][r * GSTR + 16 + 4 * (part - 4)]);
            }
            cpa16(dst, &W2[src]);
        }
    };

    float acc[2][8][4];
    #pragma unroll
    for (int i = 0; i < 2; i++)
        #pragma unroll
        for (int j = 0; j < 8; j++)
            #pragma unroll
            for (int l = 0; l < 4; l++) acc[i][j][l] = 0.f;

    load_stage(0, 0);
    asm volatile("cp.async.commit_group;\n" ::: "memory");
    load_stage(1, 1);
    asm volatile("cp.async.commit_group;\n" ::: "memory");

    for (int t = 0; t < NCHUNK; t++) {
        const int buf = t & 1;
        asm volatile("cp.async.wait_group 1;\n" ::: "memory");
        __syncthreads();

        const uint32_t aBase = s2u(Abuf[buf]) + 4 * aOff;
        const uint32_t wBase = s2u(Wbuf[buf]) + 4 * wOff;

        #pragma unroll
        for (int s = 0; s < 2; s++) {
            uint32_t ah[2][4], am[2][4];
            #pragma unroll
            for (int mi = 0; mi < 2; mi++) {
                ldm_x4(ah[mi][0], ah[mi][1], ah[mi][2], ah[mi][3],
                       aBase + 4 * (16 * mi * GSTR + 8 * s));
                ldm_x4(am[mi][0], am[mi][1], am[mi][2], am[mi][3],
                       aBase + 4 * (16 * mi * GSTR + 16 + 8 * s));
            }
            #pragma unroll
            for (int njp = 0; njp < 4; njp++) {
                uint32_t bh0, bh1, bh2, bh3, bm0, bm1, bm2, bm3;
                ldm_x4(bh0, bh1, bh2, bh3,
                       wBase + 4 * (16 * njp * GSTR + 8 * s));
                ldm_x4(bm0, bm1, bm2, bm3,
                       wBase + 4 * (16 * njp * GSTR + 16 + 8 * s));
                mma3b(acc[0][2*njp    ], ah[0], am[0], bh0, bh1, bm0, bm1);
                mma3b(acc[1][2*njp    ], ah[1], am[1], bh0, bh1, bm0, bm1);
                mma3b(acc[0][2*njp + 1], ah[0], am[0], bh2, bh3, bm2, bm3);
                mma3b(acc[1][2*njp + 1], ah[1], am[1], bh2, bh3, bm2, bm3);
            }
        }
        __syncthreads();

        if (t + 2 < NCHUNK) load_stage(t + 2, buf);
        asm volatile("cp.async.commit_group;\n" ::: "memory");
    }

    #pragma unroll
    for (int mi = 0; mi < 2; mi++) {
        int r0 = mb + wm + mi * 16 + g;
        #pragma unroll
        for (int nj = 0; nj < 8; nj++) {
            int c0 = nb + wn + nj * 8 + 2 * tg;
            float bia0 = bias[c0], bia1 = bias[c0 + 1];
            float v00 = acc[mi][nj][0] + bia0;
            float v01 = acc[mi][nj][1] + bia1;
            float v10 = acc[mi][nj][2] + bia0;
            float v11 = acc[mi][nj][3] + bia1;
            if (SPLITOUT) {
                uint32_t* C = (uint32_t*)Cout;
                uint32_t hi, mid;
                split2(v00, v01, hi, mid);
                C[(size_t)r0 * ROWU + (c0 >> 1)]       = hi;
                C[(size_t)r0 * ROWU + 256 + (c0 >> 1)] = mid;
                split2(v10, v11, hi, mid);
                C[(size_t)(r0 + 8) * ROWU + (c0 >> 1)]       = hi;
                C[(size_t)(r0 + 8) * ROWU + 256 + (c0 >> 1)] = mid;
            } else {
                float* C = (float*)Cout;
                *(float2*)&C[(size_t)r0 * Nc + c0]       = make_float2(v00, v01);
                *(float2*)&C[(size_t)(r0 + 8) * Nc + c0] = make_float2(v10, v11);
            }
        }
    }
}

// ---------------------------------------------------------------------------
// bf16-split attention with ldmatrix fetch. 128 thr / 4 warps.
// Warp owns 16 q-rows x all 32 keys -> S->P->PV stays in-lane.
// ---------------------------------------------------------------------------
#define KSTR 68                 // K smem row: [hi 32 u32][mid 32][pad 4]
#define VSTR 36                 // Vt smem row: [hi 16 u32][mid 16][pad 4]
#define KTILE (32*KSTR)
#define VTILE (64*VSTR)
#define NTILES (N_/32)

__global__ __launch_bounds__(128, 4) void attn_bf16_kernel(
    const uint32_t* __restrict__ q2, const uint32_t* __restrict__ k2,
    const uint32_t* __restrict__ v2t, uint32_t* __restrict__ ctx2)
{
    extern __shared__ uint32_t sma[];
    uint32_t* Kb[2] = { sma,             sma + KTILE };
    uint32_t* Vb[2] = { sma + 2*KTILE,   sma + 2*KTILE + VTILE };

    const int tid  = threadIdx.x;
    const int lane = tid & 31, warp = tid >> 5;
    const int g    = lane >> 2, tg = lane & 3;
    const int wm   = warp * 16;

    const int hidx = blockIdx.y;
    const int h    = hidx & (H_ - 1);
    const int tb   = hidx >> 3;
    const int tokb = tb * N_;
    const size_t headv = (size_t)hidx * (64 * 1024);
    const int q0   = blockIdx.x * 64;

    // ldmatrix per-lane offsets (u32 units within a tile buffer)
    const uint32_t kOff = (uint32_t)((lane & 7) * KSTR +
                                     ((lane >> 3) & 1) * 4 +
                                     (lane >> 4) * 8 * KSTR);
    const uint32_t vOff = (uint32_t)((lane & 7) * VSTR +
                                     ((lane >> 3) & 1) * 4 +
                                     (lane >> 4) * 8 * VSTR);

    auto load_tile = [&](int t, int buf) {
        const int k0 = 32 * t;
        #pragma unroll
        for (int l = tid; l < 512; l += 128) {   // K: 32 keys x 64 u32
            int key = l >> 4, part = l & 15;
            size_t rowb = (size_t)(tokb + k0 + key) * ROWU + h * 32;
            size_t src; uint32_t dst;
            if (part < 8) {
                src = rowb + 4 * part;
                dst = s2u(&Kb[buf][key * KSTR + 4 * part]);
            } else {
                src = rowb + 256 + 4 * (part - 8);
                dst = s2u(&Kb[buf][key * KSTR + 32 + 4 * (part - 8)]);
            }
            cpa16(dst, &k2[src]);
        }
        #pragma unroll
        for (int l = tid; l < 512; l += 128) {   // Vt: 64 ch x 32 u32
            int ch = l >> 3, part = l & 7;
            size_t vrow = headv + (size_t)ch * 1024;
            size_t src; uint32_t dst;
            if (part < 4) {
                src = vrow + (k0 >> 1) + 4 * part;
                dst = s2u(&Vb[buf][ch * VSTR + 4 * part]);
            } else {
                src = vrow + 512 + (k0 >> 1) + 4 * (part - 4);
                dst = s2u(&Vb[buf][ch * VSTR + 16 + 4 * (part - 4)]);
            }
            cpa16(dst, &v2t[src]);
        }
    };

    load_tile(0, 0);
    asm volatile("cp.async.commit_group;\n" ::: "memory");
    load_tile(1, 1);
    asm volatile("cp.async.commit_group;\n" ::: "memory");

    // ---- Q fragments -> registers ----
    uint32_t qh[4][4], qm[4][4];
    {
        size_t rA = (size_t)(tokb + q0 + wm + g) * ROWU + h * 32;
        size_t rB = rA + (size_t)8 * ROWU;
        #pragma unroll
        for (int s = 0; s < 4; s++) {
            qh[s][0] = q2[rA + 8*s + tg];        qh[s][1] = q2[rB + 8*s + tg];
            qh[s][2] = q2[rA + 8*s + tg + 4];    qh[s][3] = q2[rB + 8*s + tg + 4];
            qm[s][0] = q2[rA + 256 + 8*s + tg];      qm[s][1] = q2[rB + 256 + 8*s + tg];
            qm[s][2] = q2[rA + 256 + 8*s + tg + 4];  qm[s][3] = q2[rB + 256 + 8*s + tg + 4];
        }
    }

    float accPV[8][4];
    #pragma unroll
    for (int j = 0; j < 8; j++)
        #pragma unroll
        for (int l = 0; l < 4; l++) accPV[j][l] = 0.f;
    float dA = 0.f, dB = 0.f;

    for (int t = 0; t < NTILES; t++) {
        const int buf = t & 1;
        asm volatile("cp.async.wait_group 1;\n" ::: "memory");
        __syncthreads();

        const uint32_t kBase = s2u(Kb[buf]) + 4 * kOff;
        const uint32_t vBase = s2u(Vb[buf]) + 4 * vOff;

        // ---- S = Q K^T : 16 rows x 32 keys ----
        float accS[4][4];
        #pragma unroll
        for (int j = 0; j < 4; j++)
            #pragma unroll
            for (int l = 0; l < 4; l++) accS[j][l] = 0.f;

        #pragma unroll
        for (int s = 0; s < 4; s++) {
            #pragma unroll
            for (int njp = 0; njp < 2; njp++) {
                uint32_t bh0, bh1, bh2, bh3, bm0, bm1, bm2, bm3;
                ldm_x4(bh0, bh1, bh2, bh3,
                       kBase + 4 * (16 * njp * KSTR + 8 * s));
                ldm_x4(bm0, bm1, bm2, bm3,
                       kBase + 4 * (16 * njp * KSTR + 32 + 8 * s));
                mma3b(accS[2*njp    ], qh[s], qm[s], bh0, bh1, bm0, bm1);
                mma3b(accS[2*njp + 1], qh[s], qm[s], bh2, bh3, bm2, bm3);
            }
        }

        // ---- P = relu(S/8) in-lane -> A frags; denom; PV ----
        #pragma unroll
        for (int kb = 0; kb < 2; kb++) {
            float p0 = fmaxf(accS[2*kb    ][0] * 0.125f, 0.f);
            float p1 = fmaxf(accS[2*kb    ][1] * 0.125f, 0.f);
            float p2 = fmaxf(accS[2*kb    ][2] * 0.125f, 0.f);
            float p3 = fmaxf(accS[2*kb    ][3] * 0.125f, 0.f);
            float p4 = fmaxf(accS[2*kb + 1][0] * 0.125f, 0.f);
            float p5 = fmaxf(accS[2*kb + 1][1] * 0.125f, 0.f);
            float p6 = fmaxf(accS[2*kb + 1][2] * 0.125f, 0.f);
            float p7 = fmaxf(accS[2*kb + 1][3] * 0.125f, 0.f);
            dA += p0 + p1 + p4 + p5;
            dB += p2 + p3 + p6 + p7;

            uint32_t ah[4], am[4];
            split2(p0, p1, ah[0], am[0]);
            split2(p2, p3, ah[1], am[1]);
            split2(p4, p5, ah[2], am[2]);
            split2(p6, p7, ah[3], am[3]);

            #pragma unroll
            for (int njp = 0; njp < 4; njp++) {
                uint32_t bh0, bh1, bh2, bh3, bm0, bm1, bm2, bm3;
                ldm_x4(bh0, bh1, bh2, bh3,
                       vBase + 4 * (16 * njp * VSTR + 8 * kb));
                ldm_x4(bm0, bm1, bm2, bm3,
                       vBase + 4 * (16 * njp * VSTR + 16 + 8 * kb));
                mma3b(accPV[2*njp    ], ah, am, bh0, bh1, bm0, bm1);
                mma3b(accPV[2*njp + 1], ah, am, bh2, bh3, bm2, bm3);
            }
        }
        __syncthreads();

        if (t + 2 < NTILES) load_tile(t + 2, buf);
        asm volatile("cp.async.commit_group;\n" ::: "memory");
    }

    // ---- denominator reduce over tg lanes ----
    dA += __shfl_xor_sync(0xffffffffu, dA, 1);
    dA += __shfl_xor_sync(0xffffffffu, dA, 2);
    dB += __shfl_xor_sync(0xffffffffu, dB, 1);
    dB += __shfl_xor_sync(0xffffffffu, dB, 2);
    const float invA = 1.f / (dA + 1e-6f);
    const float invB = 1.f / (dB + 1e-6f);

    // ---- write ctx packed (planes) for O projection ----
    size_t rA = (size_t)(tokb + q0 + wm + g) * ROWU + h * 32;
    size_t rB = rA + (size_t)8 * ROWU;
    #pragma unroll
    for (int nj = 0; nj < 8; nj++) {
        uint32_t hi, mid;
        split2(accPV[nj][0] * invA, accPV[nj][1] * invA, hi, mid);
        ctx2[rA + 4*nj + tg]       = hi;
        ctx2[rA + 256 + 4*nj + tg] = mid;
        split2(accPV[nj][2] * invB, accPV[nj][3] * invB, hi, mid);
        ctx2[rB + 4*nj + tg]       = hi;
        ctx2[rB + 256 + 4*nj + tg] = mid;
    }
}

// ---------------------------------------------------------------------------
// Launcher. Input order: x, wq, bq, wk, bk, wv, bv, wo, bo
// ---------------------------------------------------------------------------
extern "C" void kernel_launch(void* const* d_in, const int* in_sizes, int n_in,
                              void* d_out, int out_size)
{
    const float* x  = (const float*)d_in[0];
    const float* wq = (const float*)d_in[1];
    const float* bq = (const float*)d_in[2];
    const float* wk = (const float*)d_in[3];
    const float* bk = (const float*)d_in[4];
    const float* wv = (const float*)d_in[5];
    const float* bv = (const float*)d_in[6];
    const float* wo = (const float*)d_in[7];
    const float* bo = (const float*)d_in[8];
    float* out = (float*)d_out;

    uint32_t *x2, *q2, *k2, *v2, *v2t, *wq2, *wk2, *wv2, *wo2;
    cudaGetSymbolAddress((void**)&x2,  gU_x2);
    cudaGetSymbolAddress((void**)&q2,  gU_q2);
    cudaGetSymbolAddress((void**)&k2,  gU_k2);
    cudaGetSymbolAddress((void**)&v2,  gU_v2);
    cudaGetSymbolAddress((void**)&v2t, gU_v2t);
    cudaGetSymbolAddress((void**)&wq2, gU_wq2);
    cudaGetSymbolAddress((void**)&wk2, gU_wk2);
    cudaGetSymbolAddress((void**)&wv2, gU_wv2);
    cudaGetSymbolAddress((void**)&wo2, gU_wo2);

    const int gemm_smem = 4 * GSTG * (int)sizeof(uint32_t);            // 73,728 B
    const int attn_smem = (2*KTILE + 2*VTILE) * (int)sizeof(uint32_t); // 35,840 B
    cudaFuncSetAttribute(gemm_bf16_kernel<1>,
        cudaFuncAttributeMaxDynamicSharedMemorySize, gemm_smem);
    cudaFuncSetAttribute(gemm_bf16_kernel<0>,
        cudaFuncAttributeMaxDynamicSharedMemorySize, gemm_smem);
    cudaFuncSetAttribute(attn_bf16_kernel,
        cudaFuncAttributeMaxDynamicSharedMemorySize, attn_smem);

    // ---- pack fp32 -> bf16 (hi,mid) planes ----
    {
        int npx = M_ * 256;
        pack_planes_kernel<<<(npx + 255) / 256, 256>>>(x, x2, npx);
        int npw = D_ * 256;
        pack_planes_kernel<<<(npw + 255) / 256, 256>>>(wq, wq2, npw);
        pack_planes_kernel<<<(npw + 255) / 256, 256>>>(wk, wk2, npw);
        pack_planes_kernel<<<(npw + 255) / 256, 256>>>(wv, wv2, npw);
        pack_planes_kernel<<<(npw + 255) / 256, 256>>>(wo, wo2, npw);
    }

    dim3 gProj(D_ / 128, M_ / 128);        // 4 x 128
    gemm_bf16_kernel<1><<<gProj, 256, gemm_smem>>>(x2, wq2, bq, q2, M_, D_);
    gemm_bf16_kernel<1><<<gProj, 256, gemm_smem>>>(x2, wk2, bk, k2, M_, D_);
    gemm_bf16_kernel<1><<<gProj, 256, gemm_smem>>>(x2, wv2, bv, v2, M_, D_);

    dim3 gT(T_ * B_ * H_, N_ / 32);        // 128 x 32
    transpose_v_kernel<<<gT, 128>>>(v2, v2t);

    dim3 gAttn(N_ / 64, T_ * B_ * H_);     // 16 x 128
    attn_bf16_kernel<<<gAttn, 128, attn_smem>>>(q2, k2, v2t, x2);  // ctx -> x2

    gemm_bf16_kernel<0><<<gProj, 256, gemm_smem>>>(x2, wo2, bo, out, M_, D_);
}

// round 10
// speedup vs baseline: 3.4594x; 1.0255x over previous
#include <cuda_runtime.h>
#include <cuda_bf16.h>
#include <cstdint>

// Problem constants
#define T_  4
#define B_  4
#define N_  1024
#define D_  512
#define H_  8
#define HD_ 64
#define M_  (T_*B_*N_)     // 16384 rows
#define ROWU 512           // packed row width in u32: [hi 256][mid 256]

// Scratch (no cudaMalloc). Packed bf16 (hi,mid) plane buffers, u32 units.
__device__ uint32_t gU_x2  [(size_t)M_*ROWU];   // x packed; reused as ctx packed
__device__ uint32_t gU_q2  [(size_t)M_*ROWU];
__device__ uint32_t gU_k2  [(size_t)M_*ROWU];
__device__ uint32_t gU_v2  [(size_t)M_*ROWU];
__device__ uint32_t gU_v2t [(size_t)M_*ROWU];   // V transposed per head
__device__ uint32_t gU_wqkv2[(size_t)3*D_*ROWU]; // wq|wk|wv packed, rows 0..1535
__device__ uint32_t gU_wo2 [(size_t)D_*ROWU];
__device__ float    g_bias3[3*D_];               // bq|bk|bv

// ---------------------------------------------------------------------------
// bf16 split + mma + ldmatrix helpers
// ---------------------------------------------------------------------------
__device__ __forceinline__ uint32_t bpack(__nv_bfloat16 a, __nv_bfloat16 b) {
    return (uint32_t)__bfloat16_as_ushort(a) |
           ((uint32_t)__bfloat16_as_ushort(b) << 16);
}
__device__ __forceinline__ void split2(float x0, float x1,
                                       uint32_t& hi, uint32_t& mid) {
    __nv_bfloat16 h0 = __float2bfloat16(x0);
    __nv_bfloat16 h1 = __float2bfloat16(x1);
    __nv_bfloat16 m0 = __float2bfloat16(x0 - __bfloat162float(h0));
    __nv_bfloat16 m1 = __float2bfloat16(x1 - __bfloat162float(h1));
    hi = bpack(h0, h1); mid = bpack(m0, m1);
}
__device__ __forceinline__ void mma_bf16(float c[4], const uint32_t a[4],
                                         uint32_t b0, uint32_t b1) {
    asm volatile(
        "mma.sync.aligned.m16n8k16.row.col.f32.bf16.bf16.f32 "
        "{%0,%1,%2,%3}, {%4,%5,%6,%7}, {%8,%9}, {%0,%1,%2,%3};"
        : "+f"(c[0]), "+f"(c[1]), "+f"(c[2]), "+f"(c[3])
        : "r"(a[0]), "r"(a[1]), "r"(a[2]), "r"(a[3]), "r"(b0), "r"(b1));
}
__device__ __forceinline__ void mma3b(float c[4],
                                      const uint32_t ah[4], const uint32_t am[4],
                                      uint32_t bh0, uint32_t bh1,
                                      uint32_t bm0, uint32_t bm1) {
    mma_bf16(c, ah, bh0, bh1);
    mma_bf16(c, ah, bm0, bm1);
    mma_bf16(c, am, bh0, bh1);
}
__device__ __forceinline__ void ldm_x4(uint32_t& r0, uint32_t& r1,
                                       uint32_t& r2, uint32_t& r3, uint32_t addr) {
    asm volatile("ldmatrix.sync.aligned.m8n8.x4.shared.b16 {%0,%1,%2,%3}, [%4];"
                 : "=r"(r0), "=r"(r1), "=r"(r2), "=r"(r3) : "r"(addr));
}
__device__ __forceinline__ void cpa16(uint32_t saddr, const void* gptr) {
    asm volatile("cp.async.cg.shared.global [%0], [%1], 16;\n"
                 :: "r"(saddr), "l"(gptr));
}
__device__ __forceinline__ uint32_t s2u(const void* p) {
    return (uint32_t)__cvta_generic_to_shared(p);
}

// ---------------------------------------------------------------------------
// Fused pack: one launch packs x + wq/wk/wv (-> wqkv2) + wo (-> wo2)
// and concatenates biases. One float4 (2 pairs) per thread.
// ---------------------------------------------------------------------------
#define XQ_ (M_*128)     // x quads
#define WQ_ (D_*128)     // quads per weight matrix
#define PACK_TOTAL (XQ_ + 4*WQ_)

__global__ void pack_all_kernel(
    const float* __restrict__ x,
    const float* __restrict__ wq, const float* __restrict__ wk,
    const float* __restrict__ wv, const float* __restrict__ wo,
    const float* __restrict__ bq, const float* __restrict__ bk,
    const float* __restrict__ bv,
    uint32_t* __restrict__ x2, uint32_t* __restrict__ wqkv2,
    uint32_t* __restrict__ wo2, float* __restrict__ bias3)
{
    int q = blockIdx.x * blockDim.x + threadIdx.x;
    if (q < 3 * D_)
        bias3[q] = (q < D_) ? bq[q] : (q < 2*D_) ? bk[q - D_] : bv[q - 2*D_];
    if (q >= PACK_TOTAL) return;

    const float* src; uint32_t* dst; int j;
    if (q < XQ_) { src = x; dst = x2; j = q; }
    else {
        int w = (q - XQ_) >> 16;           // WQ_ = 65536
        j = (q - XQ_) & 65535;
        src = (w == 0) ? wq : (w == 1) ? wk : (w == 2) ? wv : wo;
        dst = (w < 3) ? wqkv2 + (size_t)w * D_ * ROWU : wo2;
    }
    float4 s = ((const float4*)src)[j];
    int p = 2 * j, r = p >> 8, c = p & 255;
    uint32_t h0, m0, h1, m1;
    split2(s.x, s.y, h0, m0);
    split2(s.z, s.w, h1, m1);
    *(uint2*)&dst[(size_t)r * ROWU + c]       = make_uint2(h0, h1);
    *(uint2*)&dst[(size_t)r * ROWU + 256 + c] = make_uint2(m0, m1);
}

// ---------------------------------------------------------------------------
// V transpose: v2 [tok][ch planes] -> v2t [head][ch][hi 512 | mid 512]
// ---------------------------------------------------------------------------
__global__ void transpose_v_kernel(const uint32_t* __restrict__ v2,
                                   uint32_t* __restrict__ v2t)
{
    __shared__ uint32_t ts[32][65];

    const int head = blockIdx.x;
    const int h    = head & (H_ - 1);
    const int tb   = head >> 3;
    const int k0   = blockIdx.y * 32;
    const int tokb = tb * N_ + k0;

    for (int i = threadIdx.x; i < 32 * 64; i += 128) {
        int tok = i >> 6, c = i & 63;
        size_t src = (size_t)(tokb + tok) * ROWU + h * 32 +
                     (c < 32 ? c : 256 + (c - 32));
        ts[tok][c] = v2[src];
    }
    __syncthreads();

    const size_t outb = (size_t)head * (64 * 1024);
    for (int i = threadIdx.x; i < 64 * 32; i += 128) {
        int ch = i >> 5, rest = i & 31;
        int plane = rest >> 4, j = rest & 15;
        uint32_t w0 = ts[2 * j    ][plane * 32 + (ch >> 1)];
        uint32_t w1 = ts[2 * j + 1][plane * 32 + (ch >> 1)];
        uint16_t e0 = (ch & 1) ? (uint16_t)(w0 >> 16) : (uint16_t)(w0 & 0xffff);
        uint16_t e1 = (ch & 1) ? (uint16_t)(w1 >> 16) : (uint16_t)(w1 & 0xffff);
        v2t[outb + (size_t)ch * 1024 + plane * 512 + (k0 >> 1) + j] =
            (uint32_t)e0 | ((uint32_t)e1 << 16);
    }
}

// ---------------------------------------------------------------------------
// GEMM common: block 128x128, 256 thr (4Mx2N warps), 2-stage cp.async,
// ldmatrix operand fetch. Smem chunk row: [hi 16 u32][mid 16][pad 4] = 36.
// ---------------------------------------------------------------------------
#define GSTR  36
#define GSTG  (128*GSTR)
#define NCHUNK 16

// ---- body macro pieces shared by both GEMM kernels -----------------------
#define GEMM_PROLOG(A2PTR, W2PTR)                                              \
    extern __shared__ uint32_t smg[];                                          \
    uint32_t* Abuf[2] = { smg,            smg + GSTG };                        \
    uint32_t* Wbuf[2] = { smg + 2*GSTG,   smg + 3*GSTG };                      \
    const int tid  = threadIdx.x;                                              \
    const int lane = tid & 31, warp = tid >> 5;                                \
    const int g    = lane >> 2, tg = lane & 3;                                 \
    const int wm   = (warp >> 1) * 32;                                         \
    const int wn   = (warp & 1) * 64;                                          \
    const int mb   = blockIdx.y * 128, nb = blockIdx.x * 128;                  \
    const uint32_t aOff = (uint32_t)((wm + (lane & 15)) * GSTR + (lane >> 4) * 4); \
    const uint32_t wOff = (uint32_t)((wn + (lane & 7)) * GSTR +                \
                                     ((lane >> 3) & 1) * 4 +                   \
                                     (lane >> 4) * 8 * GSTR);                  \
    auto load_stage = [&](int t, int buf) {                                    \
        _Pragma("unroll")                                                      \
        for (int l = tid; l < 1024; l += 256) {                                \
            int r = l >> 3, part = l & 7;                                      \
            size_t src; uint32_t dst;                                          \
            if (part < 4) {                                                    \
                src = (size_t)(mb + r) * ROWU + 16 * t + 4 * part;             \
                dst = s2u(&Abuf[buf][r * GSTR + 4 * part]);                    \
            } else {                                                           \
                src = (size_t)(mb + r) * ROWU + 256 + 16 * t + 4 * (part - 4); \
                dst = s2u(&Abuf[buf][r * GSTR + 16 + 4 * (part - 4)]);         \
            }                                                                  \
            cpa16(dst, &(A2PTR)[src]);                                         \
        }                                                                      \
        _Pragma("unroll")                                                      \
        for (int l = tid; l < 1024; l += 256) {                                \
            int r = l >> 3, part = l & 7;                                      \
            size_t src; uint32_t dst;                                          \
            if (part < 4) {                                                    \
                src = (size_t)(nb + r) * ROWU + 16 * t + 4 * part;             \
                dst = s2u(&Wbuf[buf][r * GSTR + 4 * part]);                    \
            } else {                                                           \
                src = (size_t)(nb + r) * ROWU + 256 + 16 * t + 4 * (part - 4); \
                dst = s2u(&Wbuf[buf][r * GSTR + 16 + 4 * (part - 4)]);         \
            }                                                                  \
            cpa16(dst, &(W2PTR)[src]);                                         \
        }                                                                      \
    };                                                                         \
    float acc[2][8][4];                                                        \
    _Pragma("unroll")                                                          \
    for (int i = 0; i < 2; i++)                                                \
        _Pragma("unroll")                                                      \
        for (int j = 0; j < 8; j++)                                            \
            _Pragma("unroll")                                                  \
            for (int l = 0; l < 4; l++) acc[i][j][l] = 0.f;                    \
    load_stage(0, 0);                                                          \
    asm volatile("cp.async.commit_group;\n" ::: "memory");                     \
    load_stage(1, 1);                                                          \
    asm volatile("cp.async.commit_group;\n" ::: "memory");                     \
    for (int t = 0; t < NCHUNK; t++) {                                         \
        const int buf = t & 1;                                                 \
        asm volatile("cp.async.wait_group 1;\n" ::: "memory");                 \
        __syncthreads();                                                       \
        const uint32_t aBase = s2u(Abuf[buf]) + 4 * aOff;                      \
        const uint32_t wBase = s2u(Wbuf[buf]) + 4 * wOff;                      \
        _Pragma("unroll")                                                      \
        for (int s = 0; s < 2; s++) {                                          \
            uint32_t ah[2][4], am[2][4];                                       \
            _Pragma("unroll")                                                  \
            for (int mi = 0; mi < 2; mi++) {                                   \
                ldm_x4(ah[mi][0], ah[mi][1], ah[mi][2], ah[mi][3],             \
                       aBase + 4 * (16 * mi * GSTR + 8 * s));                  \
                ldm_x4(am[mi][0], am[mi][1], am[mi][2], am[mi][3],             \
                       aBase + 4 * (16 * mi * GSTR + 16 + 8 * s));             \
            }                                                                  \
            _Pragma("unroll")                                                  \
            for (int njp = 0; njp < 4; njp++) {                                \
                uint32_t bh0, bh1, bh2, bh3, bm0, bm1, bm2, bm3;               \
                ldm_x4(bh0, bh1, bh2, bh3,                                     \
                       wBase + 4 * (16 * njp * GSTR + 8 * s));                 \
                ldm_x4(bm0, bm1, bm2, bm3,                                     \
                       wBase + 4 * (16 * njp * GSTR + 16 + 8 * s));            \
                mma3b(acc[0][2*njp    ], ah[0], am[0], bh0, bh1, bm0, bm1);    \
                mma3b(acc[1][2*njp    ], ah[1], am[1], bh0, bh1, bm0, bm1);    \
                mma3b(acc[0][2*njp + 1], ah[0], am[0], bh2, bh3, bm2, bm3);    \
                mma3b(acc[1][2*njp + 1], ah[1], am[1], bh2, bh3, bm2, bm3);    \
            }                                                                  \
        }                                                                      \
        __syncthreads();                                                       \
        if (t + 2 < NCHUNK) load_stage(t + 2, buf);                            \
        asm volatile("cp.async.commit_group;\n" ::: "memory");                 \
    }

// ---------------------------------------------------------------------------
// Fused QKV GEMM: W = wqkv2 (1536 rows), bias3 concat, split-packed output
// routed to q2/k2/v2 by column segment. Grid (12, 128).
// ---------------------------------------------------------------------------
__global__ __launch_bounds__(256, 2) void gemm_qkv_kernel(
    const uint32_t* __restrict__ A2, const uint32_t* __restrict__ W2,
    const float* __restrict__ bias3,
    uint32_t* __restrict__ q2, uint32_t* __restrict__ k2,
    uint32_t* __restrict__ v2)
{
    GEMM_PROLOG(A2, W2)

    const int seg = nb >> 9;                       // 0=q,1=k,2=v (const/block)
    uint32_t* C = (seg == 0) ? q2 : (seg == 1) ? k2 : v2;

    #pragma unroll
    for (int mi = 0; mi < 2; mi++) {
        int r0 = mb + wm + mi * 16 + g;
        #pragma unroll
        for (int nj = 0; nj < 8; nj++) {
            int c0g = nb + wn + nj * 8 + 2 * tg;   // global col in [0,1536)
            int c0  = c0g & 511;                   // col within segment
            float bia0 = bias3[c0g], bia1 = bias3[c0g + 1];
            float v00 = acc[mi][nj][0] + bia0;
            float v01 = acc[mi][nj][1] + bia1;
            float v10 = acc[mi][nj][2] + bia0;
            float v11 = acc[mi][nj][3] + bia1;
            uint32_t hi, mid;
            split2(v00, v01, hi, mid);
            C[(size_t)r0 * ROWU + (c0 >> 1)]       = hi;
            C[(size_t)r0 * ROWU + 256 + (c0 >> 1)] = mid;
            split2(v10, v11, hi, mid);
            C[(size_t)(r0 + 8) * ROWU + (c0 >> 1)]       = hi;
            C[(size_t)(r0 + 8) * ROWU + 256 + (c0 >> 1)] = mid;
        }
    }
}

// ---------------------------------------------------------------------------
// O projection GEMM: plain float output. Grid (4, 128).
// ---------------------------------------------------------------------------
__global__ __launch_bounds__(256, 2) void gemm_o_kernel(
    const uint32_t* __restrict__ A2, const uint32_t* __restrict__ W2,
    const float* __restrict__ bias, float* __restrict__ C)
{
    GEMM_PROLOG(A2, W2)

    #pragma unroll
    for (int mi = 0; mi < 2; mi++) {
        int r0 = mb + wm + mi * 16 + g;
        #pragma unroll
        for (int nj = 0; nj < 8; nj++) {
            int c0 = nb + wn + nj * 8 + 2 * tg;
            float bia0 = bias[c0], bia1 = bias[c0 + 1];
            *(float2*)&C[(size_t)r0 * D_ + c0] =
                make_float2(acc[mi][nj][0] + bia0, acc[mi][nj][1] + bia1);
            *(float2*)&C[(size_t)(r0 + 8) * D_ + c0] =
                make_float2(acc[mi][nj][2] + bia0, acc[mi][nj][3] + bia1);
        }
    }
}

// ---------------------------------------------------------------------------
// bf16-split attention, 3-stage cp.async pipeline. 128 thr / 4 warps.
// Warp owns 16 q-rows x all 32 keys -> S->P->PV stays in-lane.
// ---------------------------------------------------------------------------
#define KSTR 68                 // K smem row: [hi 32 u32][mid 32][pad 4]
#define VSTR 36                 // Vt smem row: [hi 16 u32][mid 16][pad 4]
#define KTILE (32*KSTR)
#define VTILE (64*VSTR)
#define NSTAGE 3
#define NTILES (N_/32)

__global__ __launch_bounds__(128, 4) void attn_bf16_kernel(
    const uint32_t* __restrict__ q2, const uint32_t* __restrict__ k2,
    const uint32_t* __restrict__ v2t, uint32_t* __restrict__ ctx2)
{
    extern __shared__ uint32_t sma[];
    uint32_t* Kb[NSTAGE];
    uint32_t* Vb[NSTAGE];
    #pragma unroll
    for (int i = 0; i < NSTAGE; i++) {
        Kb[i] = sma + i * KTILE;
        Vb[i] = sma + NSTAGE * KTILE + i * VTILE;
    }

    const int tid  = threadIdx.x;
    const int lane = tid & 31, warp = tid >> 5;
    const int g    = lane >> 2, tg = lane & 3;
    const int wm   = warp * 16;

    const int hidx = blockIdx.y;
    const int h    = hidx & (H_ - 1);
    const int tb   = hidx >> 3;
    const int tokb = tb * N_;
    const size_t headv = (size_t)hidx * (64 * 1024);
    const int q0   = blockIdx.x * 64;

    const uint32_t kOff = (uint32_t)((lane & 7) * KSTR +
                                     ((lane >> 3) & 1) * 4 +
                                     (lane >> 4) * 8 * KSTR);
    const uint32_t vOff = (uint32_t)((lane & 7) * VSTR +
                                     ((lane >> 3) & 1) * 4 +
                                     (lane >> 4) * 8 * VSTR);

    auto load_tile = [&](int t, int buf) {
        const int k0 = 32 * t;
        #pragma unroll
        for (int l = tid; l < 512; l += 128) {   // K: 32 keys x 64 u32
            int key = l >> 4, part = l & 15;
            size_t rowb = (size_t)(tokb + k0 + key) * ROWU + h * 32;
            size_t src; uint32_t dst;
            if (part < 8) {
                src = rowb + 4 * part;
                dst = s2u(&Kb[buf][key * KSTR + 4 * part]);
            } else {
                src = rowb + 256 + 4 * (part - 8);
                dst = s2u(&Kb[buf][key * KSTR + 32 + 4 * (part - 8)]);
            }
            cpa16(dst, &k2[src]);
        }
        #pragma unroll
        for (int l = tid; l < 512; l += 128) {   // Vt: 64 ch x 32 u32
            int ch = l >> 3, part = l & 7;
            size_t vrow = headv + (size_t)ch * 1024;
            size_t src; uint32_t dst;
            if (part < 4) {
                src = vrow + (k0 >> 1) + 4 * part;
                dst = s2u(&Vb[buf][ch * VSTR + 4 * part]);
            } else {
                src = vrow + 512 + (k0 >> 1) + 4 * (part - 4);
                dst = s2u(&Vb[buf][ch * VSTR + 16 + 4 * (part - 4)]);
            }
            cpa16(dst, &v2t[src]);
        }
    };

    #pragma unroll
    for (int p = 0; p < NSTAGE; p++) {
        load_tile(p, p);
        asm volatile("cp.async.commit_group;\n" ::: "memory");
    }

    // ---- Q fragments -> registers ----
    uint32_t qh[4][4], qm[4][4];
    {
        size_t rA = (size_t)(tokb + q0 + wm + g) * ROWU + h * 32;
        size_t rB = rA + (size_t)8 * ROWU;
        #pragma unroll
        for (int s = 0; s < 4; s++) {
            qh[s][0] = q2[rA + 8*s + tg];        qh[s][1] = q2[rB + 8*s + tg];
            qh[s][2] = q2[rA + 8*s + tg + 4];    qh[s][3] = q2[rB + 8*s + tg + 4];
            qm[s][0] = q2[rA + 256 + 8*s + tg];      qm[s][1] = q2[rB + 256 + 8*s + tg];
            qm[s][2] = q2[rA + 256 + 8*s + tg + 4];  qm[s][3] = q2[rB + 256 + 8*s + tg + 4];
        }
    }

    float accPV[8][4];
    #pragma unroll
    for (int j = 0; j < 8; j++)
        #pragma unroll
        for (int l = 0; l < 4; l++) accPV[j][l] = 0.f;
    float dA = 0.f, dB = 0.f;

    int buf = 0;
    for (int t = 0; t < NTILES; t++) {
        asm volatile("cp.async.wait_group 2;\n" ::: "memory");
        __syncthreads();

        const uint32_t kBase = s2u(Kb[buf]) + 4 * kOff;
        const uint32_t vBase = s2u(Vb[buf]) + 4 * vOff;

        // ---- S = Q K^T : 16 rows x 32 keys ----
        float accS[4][4];
        #pragma unroll
        for (int j = 0; j < 4; j++)
            #pragma unroll
            for (int l = 0; l < 4; l++) accS[j][l] = 0.f;

        #pragma unroll
        for (int s = 0; s < 4; s++) {
            #pragma unroll
            for (int njp = 0; njp < 2; njp++) {
                uint32_t bh0, bh1, bh2, bh3, bm0, bm1, bm2, bm3;
                ldm_x4(bh0, bh1, bh2, bh3,
                       kBase + 4 * (16 * njp * KSTR + 8 * s));
                ldm_x4(bm0, bm1, bm2, bm3,
                       kBase + 4 * (16 * njp * KSTR + 32 + 8 * s));
                mma3b(accS[2*njp    ], qh[s], qm[s], bh0, bh1, bm0, bm1);
                mma3b(accS[2*njp + 1], qh[s], qm[s], bh2, bh3, bm2, bm3);
            }
        }

        // ---- P = relu(S/8) in-lane -> A frags; denom; PV ----
        #pragma unroll
        for (int kb = 0; kb < 2; kb++) {
            float p0 = fmaxf(accS[2*kb    ][0] * 0.125f, 0.f);
            float p1 = fmaxf(accS[2*kb    ][1] * 0.125f, 0.f);
            float p2 = fmaxf(accS[2*kb    ][2] * 0.125f, 0.f);
            float p3 = fmaxf(accS[2*kb    ][3] * 0.125f, 0.f);
            float p4 = fmaxf(accS[2*kb + 1][0] * 0.125f, 0.f);
            float p5 = fmaxf(accS[2*kb + 1][1] * 0.125f, 0.f);
            float p6 = fmaxf(accS[2*kb + 1][2] * 0.125f, 0.f);
            float p7 = fmaxf(accS[2*kb + 1][3] * 0.125f, 0.f);
            dA += p0 + p1 + p4 + p5;
            dB += p2 + p3 + p6 + p7;

            uint32_t ah[4], am[4];
            split2(p0, p1, ah[0], am[0]);
            split2(p2, p3, ah[1], am[1]);
            split2(p4, p5, ah[2], am[2]);
            split2(p6, p7, ah[3], am[3]);

            #pragma unroll
            for (int njp = 0; njp < 4; njp++) {
                uint32_t bh0, bh1, bh2, bh3, bm0, bm1, bm2, bm3;
                ldm_x4(bh0, bh1, bh2, bh3,
                       vBase + 4 * (16 * njp * VSTR + 8 * kb));
                ldm_x4(bm0, bm1, bm2, bm3,
                       vBase + 4 * (16 * njp * VSTR + 16 + 8 * kb));
                mma3b(accPV[2*njp    ], ah, am, bh0, bh1, bm0, bm1);
                mma3b(accPV[2*njp + 1], ah, am, bh2, bh3, bm2, bm3);
            }
        }
        __syncthreads();   // all warps done with buf before refill

        if (t + NSTAGE < NTILES) load_tile(t + NSTAGE, buf);
        asm volatile("cp.async.commit_group;\n" ::: "memory");

        buf = (buf == NSTAGE - 1) ? 0 : buf + 1;
    }

    // ---- denominator reduce over tg lanes ----
    dA += __shfl_xor_sync(0xffffffffu, dA, 1);
    dA += __shfl_xor_sync(0xffffffffu, dA, 2);
    dB += __shfl_xor_sync(0xffffffffu, dB, 1);
    dB += __shfl_xor_sync(0xffffffffu, dB, 2);
    const float invA = 1.f / (dA + 1e-6f);
    const float invB = 1.f / (dB + 1e-6f);

    // ---- write ctx packed (planes) for O projection ----
    size_t rA = (size_t)(tokb + q0 + wm + g) * ROWU + h * 32;
    size_t rB = rA + (size_t)8 * ROWU;
    #pragma unroll
    for (int nj = 0; nj < 8; nj++) {
        uint32_t hi, mid;
        split2(accPV[nj][0] * invA, accPV[nj][1] * invA, hi, mid);
        ctx2[rA + 4*nj + tg]       = hi;
        ctx2[rA + 256 + 4*nj + tg] = mid;
        split2(accPV[nj][2] * invB, accPV[nj][3] * invB, hi, mid);
        ctx2[rB + 4*nj + tg]       = hi;
        ctx2[rB + 256 + 4*nj + tg] = mid;
    }
}

// ---------------------------------------------------------------------------
// Launcher. Input order: x, wq, bq, wk, bk, wv, bv, wo, bo
// ---------------------------------------------------------------------------
extern "C" void kernel_launch(void* const* d_in, const int* in_sizes, int n_in,
                              void* d_out, int out_size)
{
    const float* x  = (const float*)d_in[0];
    const float* wq = (const float*)d_in[1];
    const float* bq = (const float*)d_in[2];
    const float* wk = (const float*)d_in[3];
    const float* bk = (const float*)d_in[4];
    const float* wv = (const float*)d_in[5];
    const float* bv = (const float*)d_in[6];
    const float* wo = (const float*)d_in[7];
    const float* bo = (const float*)d_in[8];
    float* out = (float*)d_out;

    uint32_t *x2, *q2, *k2, *v2, *v2t, *wqkv2, *wo2;
    float* bias3;
    cudaGetSymbolAddress((void**)&x2,    gU_x2);
    cudaGetSymbolAddress((void**)&q2,    gU_q2);
    cudaGetSymbolAddress((void**)&k2,    gU_k2);
    cudaGetSymbolAddress((void**)&v2,    gU_v2);
    cudaGetSymbolAddress((void**)&v2t,   gU_v2t);
    cudaGetSymbolAddress((void**)&wqkv2, gU_wqkv2);
    cudaGetSymbolAddress((void**)&wo2,   gU_wo2);
    cudaGetSymbolAddress((void**)&bias3, g_bias3);

    const int gemm_smem = 4 * GSTG * (int)sizeof(uint32_t);                // 73,728 B
    const int attn_smem = NSTAGE * (KTILE + VTILE) * (int)sizeof(uint32_t); // 53,760 B
    cudaFuncSetAttribute(gemm_qkv_kernel,
        cudaFuncAttributeMaxDynamicSharedMemorySize, gemm_smem);
    cudaFuncSetAttribute(gemm_o_kernel,
        cudaFuncAttributeMaxDynamicSharedMemorySize, gemm_smem);
    cudaFuncSetAttribute(attn_bf16_kernel,
        cudaFuncAttributeMaxDynamicSharedMemorySize, attn_smem);

    // ---- fused pack (x + 4 weights + bias concat) ----
    pack_all_kernel<<<PACK_TOTAL / 256, 256>>>(
        x, wq, wk, wv, wo, bq, bk, bv, x2, wqkv2, wo2, bias3);

    // ---- fused QKV projection ----
    dim3 gQKV(3 * D_ / 128, M_ / 128);     // 12 x 128
    gemm_qkv_kernel<<<gQKV, 256, gemm_smem>>>(x2, wqkv2, bias3, q2, k2, v2);

    dim3 gT(T_ * B_ * H_, N_ / 32);        // 128 x 32
    transpose_v_kernel<<<gT, 128>>>(v2, v2t);

    dim3 gAttn(N_ / 64, T_ * B_ * H_);     // 16 x 128
    attn_bf16_kernel<<<gAttn, 128, attn_smem>>>(q2, k2, v2t, x2);  // ctx -> x2

    dim3 gO(D_ / 128, M_ / 128);           // 4 x 128
    gemm_o_kernel<<<gO, 256, gemm_smem>>>(x2, wo2, bo, out);
}